// round 1
// baseline (speedup 1.0000x reference)
#include <cuda_runtime.h>
#include <math.h>

#define D 768
#define NH 12
#define DH 64
#define NMAX 8192

// scratch (device globals; no allocation allowed)
__device__ float g_k[NMAX * D];
__device__ float g_v[NMAX * D];
__device__ float g_q[NMAX * D];
__device__ float g_ctx[NMAX * D];
__device__ int g_idx[NMAX + 1];
__device__ unsigned char g_npad[NMAX];

// ---------------------------------------------------------------------------
// pad mask: npad[p] = (input_ids[p] != pad). Handles int32 or int64 ids.
// Detection: all ids >= 1, so if raw_i32[1] == 0 the array must be int64
// (little-endian high word of ids[0]).
// ---------------------------------------------------------------------------
__global__ void padmask_kernel(const int* __restrict__ ids_raw, int n,
                               const int* __restrict__ padp,
                               unsigned char* __restrict__ npad) {
    int p = blockIdx.x * blockDim.x + threadIdx.x;
    if (p >= n) return;
    int pad = padp[0];  // low word correct for int32 or small int64
    bool is64 = (n > 1) && (ids_raw[1] == 0);
    long long v = is64 ? ((const long long*)ids_raw)[p] : (long long)ids_raw[p];
    npad[p] = (v != (long long)pad) ? 1 : 0;
}

// ---------------------------------------------------------------------------
// segment scan: idx[r] = position of r-th query_mask==1; idx[f] = n
// single block, tiny work (n = 8192)
// ---------------------------------------------------------------------------
__global__ void scan_kernel(const int* __restrict__ qm, int n, int f,
                            int* __restrict__ idxout) {
    __shared__ int cnts[256];
    __shared__ int pre[257];
    int t = threadIdx.x;
    int per = (n + 255) / 256;
    int s = t * per;
    int e = s + per; if (e > n) e = n;
    int c = 0;
    for (int p = s; p < e; p++) c += (qm[p] != 0);
    cnts[t] = c;
    __syncthreads();
    if (t == 0) {
        pre[0] = 0;
        for (int i = 0; i < 256; i++) pre[i + 1] = pre[i] + cnts[i];
    }
    __syncthreads();
    int rank = pre[t];
    for (int p = s; p < e; p++)
        if (qm[p] != 0) idxout[rank++] = p;
    if (t == 0) idxout[f] = n;
}

// ---------------------------------------------------------------------------
// C[M,N] = A[M,K] @ B[N,K]^T + bias   (both K-major, NT GEMM)
// optional rowmap: A logical row m -> physical row rowmap[m] (Q gather)
// 128x128 block tile, BK=16, 256 threads, 8x8 per-thread tile.
// ---------------------------------------------------------------------------
#define BM 128
#define BN 128
#define BK 16

__global__ __launch_bounds__(256)
void gemm_nt(const float* __restrict__ A, const float* __restrict__ B,
             const float* __restrict__ bias, float* __restrict__ C,
             int M, int N, int K, const int* __restrict__ rowmap) {
    __shared__ float As[BK][BM];
    __shared__ float Bs[BK][BN];
    int tid = threadIdx.x;
    int tx = tid % 16;
    int ty = tid / 16;
    int m0 = blockIdx.y * BM;
    int n0 = blockIdx.x * BN;

    float acc[8][8];
#pragma unroll
    for (int i = 0; i < 8; i++)
#pragma unroll
        for (int j = 0; j < 8; j++) acc[i][j] = 0.f;

    for (int k0 = 0; k0 < K; k0 += BK) {
        // load A tile (128 rows x 16 cols = 512 float4)
#pragma unroll
        for (int i = 0; i < 2; i++) {
            int v4 = tid + i * 256;
            int r = v4 >> 2;
            int c4 = (v4 & 3) * 4;
            float4 val = make_float4(0.f, 0.f, 0.f, 0.f);
            int gr = m0 + r;
            if (gr < M) {
                int ar = rowmap ? rowmap[gr] : gr;
                val = *(const float4*)(A + (size_t)ar * K + k0 + c4);
            }
            As[c4 + 0][r] = val.x;
            As[c4 + 1][r] = val.y;
            As[c4 + 2][r] = val.z;
            As[c4 + 3][r] = val.w;
        }
        // load B tile
#pragma unroll
        for (int i = 0; i < 2; i++) {
            int v4 = tid + i * 256;
            int r = v4 >> 2;
            int c4 = (v4 & 3) * 4;
            float4 val = make_float4(0.f, 0.f, 0.f, 0.f);
            int gr = n0 + r;
            if (gr < N) {
                val = *(const float4*)(B + (size_t)gr * K + k0 + c4);
            }
            Bs[c4 + 0][r] = val.x;
            Bs[c4 + 1][r] = val.y;
            Bs[c4 + 2][r] = val.z;
            Bs[c4 + 3][r] = val.w;
        }
        __syncthreads();
#pragma unroll
        for (int k = 0; k < BK; k++) {
            float a[8], b[8];
            *(float4*)&a[0] = *(const float4*)&As[k][ty * 8];
            *(float4*)&a[4] = *(const float4*)&As[k][ty * 8 + 4];
            *(float4*)&b[0] = *(const float4*)&Bs[k][tx * 8];
            *(float4*)&b[4] = *(const float4*)&Bs[k][tx * 8 + 4];
#pragma unroll
            for (int i = 0; i < 8; i++)
#pragma unroll
                for (int j = 0; j < 8; j++) acc[i][j] += a[i] * b[j];
        }
        __syncthreads();
    }

#pragma unroll
    for (int i = 0; i < 8; i++) {
        int m = m0 + ty * 8 + i;
        if (m >= M) continue;
#pragma unroll
        for (int j = 0; j < 8; j += 4) {
            int nn = n0 + tx * 8 + j;
            if (nn + 3 >= N && nn >= N) continue;
            float4 o;
            o.x = acc[i][j + 0] + bias[nn + 0];
            o.y = acc[i][j + 1] + bias[nn + 1];
            o.z = acc[i][j + 2] + bias[nn + 2];
            o.w = acc[i][j + 3] + bias[nn + 3];
            *(float4*)(C + (size_t)m * N + nn) = o;
        }
    }
}

// ---------------------------------------------------------------------------
// attention: one block per feature, one warp per head.
// Normal path: softmax over valid keys in [left,right) (masked keys underflow
// to exact 0 in the reference fp32 softmax, so equivalent).
// Empty path (all keys padded): constant -10000 bias cancels in softmax ->
// full unmasked attention over all n keys, online softmax, lane-partitioned.
// ---------------------------------------------------------------------------
__global__ __launch_bounds__(NH * 32)
void attn_kernel(const float* __restrict__ q, const float* __restrict__ k,
                 const float* __restrict__ v, const int* __restrict__ idxarr,
                 const unsigned char* __restrict__ npad,
                 float* __restrict__ ctx, int n) {
    int i = blockIdx.x;
    int h = threadIdx.x / 32;
    int lane = threadIdx.x % 32;

    __shared__ float qsh[NH][DH];
    const float* qb = q + (size_t)i * D + h * DH;
    qsh[h][lane] = qb[lane];
    qsh[h][lane + 32] = qb[lane + 32];
    __syncwarp();

    int left = idxarr[i];
    int right = idxarr[i + 1];
    float q0 = qsh[h][lane];
    float q1 = qsh[h][lane + 32];
    const float scale = 0.125f;  // 1/sqrt(64)

    // pass 1: max over valid keys
    float m = -1e30f;
    int cnt = 0;
    for (int p = left; p < right; p++) {
        if (!npad[p]) continue;
        const float* kb = k + (size_t)p * D + h * DH;
        float part = q0 * kb[lane] + q1 * kb[lane + 32];
#pragma unroll
        for (int o = 16; o > 0; o >>= 1) part += __shfl_xor_sync(0xffffffffu, part, o);
        float s = part * scale;
        cnt++;
        if (s > m) m = s;
    }

    if (cnt > 0) {
        float l = 0.f, a0 = 0.f, a1 = 0.f;
        for (int p = left; p < right; p++) {
            if (!npad[p]) continue;
            const float* kb = k + (size_t)p * D + h * DH;
            float part = q0 * kb[lane] + q1 * kb[lane + 32];
#pragma unroll
            for (int o = 16; o > 0; o >>= 1) part += __shfl_xor_sync(0xffffffffu, part, o);
            float e = expf(part * scale - m);
            const float* vb = v + (size_t)p * D + h * DH;
            l += e;
            a0 += e * vb[lane];
            a1 += e * vb[lane + 32];
        }
        ctx[(size_t)i * D + h * DH + lane] = a0 / l;
        ctx[(size_t)i * D + h * DH + lane + 32] = a1 / l;
    } else {
        // fully-masked segment: full softmax over all n keys (bias cancels)
        float m_i = -1e30f, l_i = 0.f;
        float acc[DH];
#pragma unroll
        for (int d = 0; d < DH; d++) acc[d] = 0.f;
        for (int p = lane; p < n; p += 32) {
            const float* kb = k + (size_t)p * D + h * DH;
            float s = 0.f;
#pragma unroll
            for (int d = 0; d < DH; d++) s += qsh[h][d] * kb[d];
            s *= scale;
            if (s > m_i) {
                float c = expf(m_i - s);
                l_i *= c;
#pragma unroll
                for (int d = 0; d < DH; d++) acc[d] *= c;
                m_i = s;
            }
            float e = expf(s - m_i);
            const float* vb = v + (size_t)p * D + h * DH;
            l_i += e;
#pragma unroll
            for (int d = 0; d < DH; d++) acc[d] += e * vb[d];
        }
        // combine lane-local online states
        float M_ = m_i;
#pragma unroll
        for (int o = 16; o > 0; o >>= 1) M_ = fmaxf(M_, __shfl_xor_sync(0xffffffffu, M_, o));
        float c = expf(m_i - M_);
        float lt = l_i * c;
#pragma unroll
        for (int o = 16; o > 0; o >>= 1) lt += __shfl_xor_sync(0xffffffffu, lt, o);
#pragma unroll
        for (int d = 0; d < DH; d++) {
            float vs = acc[d] * c;
#pragma unroll
            for (int o = 16; o > 0; o >>= 1) vs += __shfl_xor_sync(0xffffffffu, vs, o);
            if (lane == 0) ctx[(size_t)i * D + h * DH + d] = vs / lt;
        }
    }
}

// ---------------------------------------------------------------------------
extern "C" void kernel_launch(void* const* d_in, const int* in_sizes, int n_in,
                              void* d_out, int out_size) {
    const float* x_qk = (const float*)d_in[0];
    const float* x_v = (const float*)d_in[1];
    const int* qm = (const int*)d_in[2];
    const int* ids = (const int*)d_in[3];
    const int* padp = (const int*)d_in[4];
    const float* Wq = (const float*)d_in[5];
    const float* bq = (const float*)d_in[6];
    const float* Wk = (const float*)d_in[7];
    const float* bk = (const float*)d_in[8];
    const float* Wv = (const float*)d_in[9];
    const float* bv = (const float*)d_in[10];
    const float* Wo = (const float*)d_in[11];
    const float* bo = (const float*)d_in[12];

    int n = in_sizes[0] / D;       // tokens
    int f = out_size / D;          // features

    float *pk, *pv, *pq, *pctx;
    int* pidx;
    unsigned char* pnp;
    cudaGetSymbolAddress((void**)&pk, g_k);
    cudaGetSymbolAddress((void**)&pv, g_v);
    cudaGetSymbolAddress((void**)&pq, g_q);
    cudaGetSymbolAddress((void**)&pctx, g_ctx);
    cudaGetSymbolAddress((void**)&pidx, g_idx);
    cudaGetSymbolAddress((void**)&pnp, g_npad);

    padmask_kernel<<<(n + 255) / 256, 256>>>(ids, n, padp, pnp);
    scan_kernel<<<1, 256>>>(qm, n, f, pidx);

    dim3 gk(D / BN, (n + BM - 1) / BM);
    gemm_nt<<<gk, 256>>>(x_qk, Wk, bk, pk, n, D, D, nullptr);
    gemm_nt<<<gk, 256>>>(x_v, Wv, bv, pv, n, D, D, nullptr);

    dim3 gq(D / BN, (f + BM - 1) / BM);
    gemm_nt<<<gq, 256>>>(x_qk, Wq, bq, pq, f, D, D, pidx);

    attn_kernel<<<f, NH * 32>>>(pq, pk, pv, pidx, pnp, pctx, n);

    gemm_nt<<<gq, 256>>>(pctx, Wo, bo, (float*)d_out, f, D, D, nullptr);
}

// round 2
// speedup vs baseline: 7.0578x; 7.0578x over previous
#include <cuda_runtime.h>
#include <math.h>

#define D 768
#define NH 12
#define DH 64
#define NMAX 8192
#define MAXE 64
#define NSPLIT 64

// scratch (device globals; no allocation allowed)
__device__ float g_k[NMAX * D];
__device__ float g_v[NMAX * D];
__device__ float g_q[NMAX * D];
__device__ float g_ctx[NMAX * D];
__device__ int g_idx[NMAX + 1];
__device__ unsigned char g_npad[NMAX];
__device__ int g_rank[NMAX];
__device__ int g_elist[MAXE];
__device__ int g_ne[1];
__device__ float g_part_ml[MAXE * NH * NSPLIT * 2];
__device__ float g_part_acc[MAXE * NH * NSPLIT * DH];

// ---------------------------------------------------------------------------
// pad mask: npad[p] = (input_ids[p] != pad). Handles int32 or int64 ids.
// ---------------------------------------------------------------------------
__global__ void padmask_kernel(const int* __restrict__ ids_raw, int n,
                               const int* __restrict__ padp,
                               unsigned char* __restrict__ npad) {
    int p = blockIdx.x * blockDim.x + threadIdx.x;
    if (p >= n) return;
    int pad = padp[0];
    bool is64 = (n > 1) && (ids_raw[1] == 0);
    long long v = is64 ? ((const long long*)ids_raw)[p] : (long long)ids_raw[p];
    npad[p] = (v != (long long)pad) ? 1 : 0;
}

// ---------------------------------------------------------------------------
// segment scan: idx[r] = position of r-th query_mask==1; idx[f] = n
// ---------------------------------------------------------------------------
__global__ void scan_kernel(const int* __restrict__ qm, int n, int f,
                            int* __restrict__ idxout, int* __restrict__ ne) {
    __shared__ int cnts[256];
    __shared__ int pre[257];
    int t = threadIdx.x;
    int per = (n + 255) / 256;
    int s = t * per;
    int e = s + per; if (e > n) e = n;
    int c = 0;
    for (int p = s; p < e; p++) c += (qm[p] != 0);
    cnts[t] = c;
    __syncthreads();
    if (t == 0) {
        pre[0] = 0;
        for (int i = 0; i < 256; i++) pre[i + 1] = pre[i] + cnts[i];
        ne[0] = 0;
    }
    __syncthreads();
    int rank = pre[t];
    for (int p = s; p < e; p++)
        if (qm[p] != 0) idxout[rank++] = p;
    if (t == 0) idxout[f] = n;
}

// ---------------------------------------------------------------------------
// mark fully-padded ("empty") features; build compacted list
// ---------------------------------------------------------------------------
__global__ void flag_empty_kernel(const int* __restrict__ idxarr,
                                  const unsigned char* __restrict__ npad, int f,
                                  int* __restrict__ rank, int* __restrict__ elist,
                                  int* __restrict__ ne) {
    int i = blockIdx.x * blockDim.x + threadIdx.x;
    if (i >= f) return;
    int L = idxarr[i], R = idxarr[i + 1];
    bool any = false;
    for (int p = L; p < R; p++) { if (npad[p]) { any = true; break; } }
    if (any) { rank[i] = -1; return; }
    int r = atomicAdd(ne, 1);
    rank[i] = r;
    if (r < MAXE) elist[r] = i;
}

// ---------------------------------------------------------------------------
// C[M,N] = A[M,K] @ B[N,K]^T + bias   (NT GEMM), templated tiles, 256 threads
// ---------------------------------------------------------------------------
template <int BM, int BN, int TM, int TN>
__global__ __launch_bounds__(256)
void gemm_nt(const float* __restrict__ A, const float* __restrict__ B,
             const float* __restrict__ bias, float* __restrict__ C,
             int M, int N, int K, const int* __restrict__ rowmap) {
    const int BK = 16;
    const int BK4 = BK / 4;
    __shared__ float As[BK][BM];
    __shared__ float Bs[BK][BN];
    int tid = threadIdx.x;
    const int NTX = BN / TN;
    int tx = tid % NTX;
    int ty = tid / NTX;
    int m0 = blockIdx.y * BM;
    int n0 = blockIdx.x * BN;

    float acc[TM][TN];
#pragma unroll
    for (int i = 0; i < TM; i++)
#pragma unroll
        for (int j = 0; j < TN; j++) acc[i][j] = 0.f;

    for (int k0 = 0; k0 < K; k0 += BK) {
#pragma unroll
        for (int v4 = tid; v4 < BM * BK4; v4 += 256) {
            int r = v4 / BK4;
            int c4 = (v4 % BK4) * 4;
            float4 val = make_float4(0.f, 0.f, 0.f, 0.f);
            int gr = m0 + r;
            if (gr < M) {
                int ar = rowmap ? rowmap[gr] : gr;
                val = *(const float4*)(A + (size_t)ar * K + k0 + c4);
            }
            As[c4 + 0][r] = val.x;
            As[c4 + 1][r] = val.y;
            As[c4 + 2][r] = val.z;
            As[c4 + 3][r] = val.w;
        }
#pragma unroll
        for (int v4 = tid; v4 < BN * BK4; v4 += 256) {
            int r = v4 / BK4;
            int c4 = (v4 % BK4) * 4;
            float4 val = make_float4(0.f, 0.f, 0.f, 0.f);
            int gr = n0 + r;
            if (gr < N) val = *(const float4*)(B + (size_t)gr * K + k0 + c4);
            Bs[c4 + 0][r] = val.x;
            Bs[c4 + 1][r] = val.y;
            Bs[c4 + 2][r] = val.z;
            Bs[c4 + 3][r] = val.w;
        }
        __syncthreads();
#pragma unroll
        for (int k = 0; k < BK; k++) {
            float a[TM], b[TN];
#pragma unroll
            for (int i = 0; i < TM; i += 4)
                *(float4*)&a[i] = *(const float4*)&As[k][ty * TM + i];
#pragma unroll
            for (int j = 0; j < TN; j += 4)
                *(float4*)&b[j] = *(const float4*)&Bs[k][tx * TN + j];
#pragma unroll
            for (int i = 0; i < TM; i++)
#pragma unroll
                for (int j = 0; j < TN; j++) acc[i][j] += a[i] * b[j];
        }
        __syncthreads();
    }

#pragma unroll
    for (int i = 0; i < TM; i++) {
        int m = m0 + ty * TM + i;
        if (m >= M) continue;
#pragma unroll
        for (int j = 0; j < TN; j += 4) {
            int nn = n0 + tx * TN + j;
            float4 o;
            o.x = acc[i][j + 0] + bias[nn + 0];
            o.y = acc[i][j + 1] + bias[nn + 1];
            o.z = acc[i][j + 2] + bias[nn + 2];
            o.w = acc[i][j + 3] + bias[nn + 3];
            *(float4*)(C + (size_t)m * N + nn) = o;
        }
    }
}

// ---------------------------------------------------------------------------
// normal attention: one block per feature, one warp per head; skips
// fully-masked features with rank < MAXE (handled by split kernels).
// ---------------------------------------------------------------------------
__global__ __launch_bounds__(NH * 32)
void attn_kernel(const float* __restrict__ q, const float* __restrict__ k,
                 const float* __restrict__ v, const int* __restrict__ idxarr,
                 const unsigned char* __restrict__ npad,
                 const int* __restrict__ rankarr,
                 float* __restrict__ ctx, int n) {
    int i = blockIdx.x;
    int rk = rankarr[i];
    if (rk >= 0 && rk < MAXE) return;  // handled by split path
    int h = threadIdx.x / 32;
    int lane = threadIdx.x % 32;

    __shared__ float qsh[NH][DH];
    const float* qb = q + (size_t)i * D + h * DH;
    qsh[h][lane] = qb[lane];
    qsh[h][lane + 32] = qb[lane + 32];
    __syncwarp();

    int left = idxarr[i];
    int right = idxarr[i + 1];
    float q0 = qsh[h][lane];
    float q1 = qsh[h][lane + 32];
    const float scale = 0.125f;

    float m = -1e30f;
    int cnt = 0;
    for (int p = left; p < right; p++) {
        if (!npad[p]) continue;
        const float* kb = k + (size_t)p * D + h * DH;
        float part = q0 * kb[lane] + q1 * kb[lane + 32];
#pragma unroll
        for (int o = 16; o > 0; o >>= 1) part += __shfl_xor_sync(0xffffffffu, part, o);
        float s = part * scale;
        cnt++;
        if (s > m) m = s;
    }

    if (cnt > 0) {
        float l = 0.f, a0 = 0.f, a1 = 0.f;
        for (int p = left; p < right; p++) {
            if (!npad[p]) continue;
            const float* kb = k + (size_t)p * D + h * DH;
            float part = q0 * kb[lane] + q1 * kb[lane + 32];
#pragma unroll
            for (int o = 16; o > 0; o >>= 1) part += __shfl_xor_sync(0xffffffffu, part, o);
            float e = expf(part * scale - m);
            const float* vb = v + (size_t)p * D + h * DH;
            l += e;
            a0 += e * vb[lane];
            a1 += e * vb[lane + 32];
        }
        ctx[(size_t)i * D + h * DH + lane] = a0 / l;
        ctx[(size_t)i * D + h * DH + lane + 32] = a1 / l;
    } else {
        // overflow fallback (rank >= MAXE): full softmax over all n keys
        float m_i = -1e30f, l_i = 0.f;
        float acc[DH];
#pragma unroll
        for (int d = 0; d < DH; d++) acc[d] = 0.f;
        for (int p = lane; p < n; p += 32) {
            const float* kb = k + (size_t)p * D + h * DH;
            float s = 0.f;
#pragma unroll
            for (int d = 0; d < DH; d++) s += qsh[h][d] * kb[d];
            s *= scale;
            if (s > m_i) {
                float c = expf(m_i - s);
                l_i *= c;
#pragma unroll
                for (int d = 0; d < DH; d++) acc[d] *= c;
                m_i = s;
            }
            float e = expf(s - m_i);
            const float* vb = v + (size_t)p * D + h * DH;
            l_i += e;
#pragma unroll
            for (int d = 0; d < DH; d++) acc[d] += e * vb[d];
        }
        float M_ = m_i;
#pragma unroll
        for (int o = 16; o > 0; o >>= 1) M_ = fmaxf(M_, __shfl_xor_sync(0xffffffffu, M_, o));
        float c = expf(m_i - M_);
        float lt = l_i * c;
#pragma unroll
        for (int o = 16; o > 0; o >>= 1) lt += __shfl_xor_sync(0xffffffffu, lt, o);
#pragma unroll
        for (int d = 0; d < DH; d++) {
            float vs = acc[d] * c;
#pragma unroll
            for (int o = 16; o > 0; o >>= 1) vs += __shfl_xor_sync(0xffffffffu, vs, o);
            if (lane == 0) ctx[(size_t)i * D + h * DH + d] = vs / lt;
        }
    }
}

// ---------------------------------------------------------------------------
// split-K flash decode for fully-masked features (bias cancels -> full softmax
// over all keys). One block per key-chunk; warp h handles head h for up to 8
// empty features at a time.
// ---------------------------------------------------------------------------
__global__ __launch_bounds__(NH * 32)
void split_attn_kernel(const float* __restrict__ q, const float* __restrict__ k,
                       const float* __restrict__ v, const int* __restrict__ elist,
                       const int* __restrict__ nep,
                       float* __restrict__ part_ml, float* __restrict__ part_acc,
                       int n) {
    int split = blockIdx.x;
    int h = threadIdx.x / 32;
    int lane = threadIdx.x % 32;
    int ne = nep[0];
    if (ne > MAXE) ne = MAXE;
    if (ne == 0) return;
    int chunk = (n + NSPLIT - 1) / NSPLIT;
    int ks = split * chunk;
    int ke = ks + chunk; if (ke > n) ke = n;
    const float scale = 0.125f;

    for (int e0 = 0; e0 < ne; e0 += 8) {
        int gs = ne - e0; if (gs > 8) gs = 8;
        float q0[8], q1[8], m_[8], l_[8], a0[8], a1[8];
#pragma unroll
        for (int j = 0; j < 8; j++) {
            if (j < gs) {
                int ft = elist[e0 + j];
                q0[j] = q[(size_t)ft * D + h * DH + lane];
                q1[j] = q[(size_t)ft * D + h * DH + lane + 32];
            } else { q0[j] = 0.f; q1[j] = 0.f; }
            m_[j] = -1e30f; l_[j] = 0.f; a0[j] = 0.f; a1[j] = 0.f;
        }
        for (int p = ks; p < ke; p++) {
            const float* kb = k + (size_t)p * D + h * DH;
            const float* vb = v + (size_t)p * D + h * DH;
            float k0 = kb[lane], k1 = kb[lane + 32];
            float v0 = vb[lane], v1 = vb[lane + 32];
            float s[8];
#pragma unroll
            for (int j = 0; j < 8; j++) s[j] = q0[j] * k0 + q1[j] * k1;
#pragma unroll
            for (int o = 16; o > 0; o >>= 1)
#pragma unroll
                for (int j = 0; j < 8; j++) s[j] += __shfl_xor_sync(0xffffffffu, s[j], o);
#pragma unroll
            for (int j = 0; j < 8; j++) {
                float sc = s[j] * scale;
                float mn = fmaxf(m_[j], sc);
                float corr = expf(m_[j] - mn);
                float e = expf(sc - mn);
                l_[j] = l_[j] * corr + e;
                a0[j] = a0[j] * corr + e * v0;
                a1[j] = a1[j] * corr + e * v1;
                m_[j] = mn;
            }
        }
#pragma unroll
        for (int j = 0; j < 8; j++) {
            if (j >= gs) continue;
            size_t base = ((size_t)(e0 + j) * NH + h) * NSPLIT + split;
            if (lane == 0) { part_ml[base * 2] = m_[j]; part_ml[base * 2 + 1] = l_[j]; }
            part_acc[base * DH + lane] = a0[j];
            part_acc[base * DH + lane + 32] = a1[j];
        }
    }
}

__global__ __launch_bounds__(DH)
void reduce_attn_kernel(const int* __restrict__ elist, const int* __restrict__ nep,
                        const float* __restrict__ part_ml,
                        const float* __restrict__ part_acc,
                        float* __restrict__ ctx) {
    int e = blockIdx.x, h = blockIdx.y;
    int ne = nep[0]; if (ne > MAXE) ne = MAXE;
    if (e >= ne) return;
    int d = threadIdx.x;
    __shared__ float wsh[NSPLIT];
    __shared__ float Lsh;
    if (d == 0) {
        float M = -1e30f;
        size_t mb = ((size_t)e * NH + h) * NSPLIT;
        for (int s = 0; s < NSPLIT; s++) {
            float m = part_ml[(mb + s) * 2];
            if (m > M) M = m;
        }
        float L = 0.f;
        for (int s = 0; s < NSPLIT; s++) {
            float m = part_ml[(mb + s) * 2];
            float l = part_ml[(mb + s) * 2 + 1];
            float w = expf(m - M);
            wsh[s] = w;
            L += w * l;
        }
        Lsh = L;
    }
    __syncthreads();
    float acc = 0.f;
    size_t ab = ((size_t)e * NH + h) * NSPLIT;
    for (int s = 0; s < NSPLIT; s++) acc += wsh[s] * part_acc[(ab + s) * DH + d];
    int ft = elist[e];
    ctx[(size_t)ft * D + h * DH + d] = acc / Lsh;
}

// ---------------------------------------------------------------------------
extern "C" void kernel_launch(void* const* d_in, const int* in_sizes, int n_in,
                              void* d_out, int out_size) {
    const float* x_qk = (const float*)d_in[0];
    const float* x_v = (const float*)d_in[1];
    const int* qm = (const int*)d_in[2];
    const int* ids = (const int*)d_in[3];
    const int* padp = (const int*)d_in[4];
    const float* Wq = (const float*)d_in[5];
    const float* bq = (const float*)d_in[6];
    const float* Wk = (const float*)d_in[7];
    const float* bk = (const float*)d_in[8];
    const float* Wv = (const float*)d_in[9];
    const float* bv = (const float*)d_in[10];
    const float* Wo = (const float*)d_in[11];
    const float* bo = (const float*)d_in[12];

    int n = in_sizes[0] / D;
    int f = out_size / D;

    float *pk, *pv, *pq, *pctx, *pml, *pacc;
    int *pidx, *prank, *pelist, *pne;
    unsigned char* pnp;
    cudaGetSymbolAddress((void**)&pk, g_k);
    cudaGetSymbolAddress((void**)&pv, g_v);
    cudaGetSymbolAddress((void**)&pq, g_q);
    cudaGetSymbolAddress((void**)&pctx, g_ctx);
    cudaGetSymbolAddress((void**)&pidx, g_idx);
    cudaGetSymbolAddress((void**)&pnp, g_npad);
    cudaGetSymbolAddress((void**)&prank, g_rank);
    cudaGetSymbolAddress((void**)&pelist, g_elist);
    cudaGetSymbolAddress((void**)&pne, g_ne);
    cudaGetSymbolAddress((void**)&pml, g_part_ml);
    cudaGetSymbolAddress((void**)&pacc, g_part_acc);

    padmask_kernel<<<(n + 255) / 256, 256>>>(ids, n, padp, pnp);
    scan_kernel<<<1, 256>>>(qm, n, f, pidx, pne);
    flag_empty_kernel<<<(f + 255) / 256, 256>>>(pidx, pnp, f, prank, pelist, pne);

    dim3 gk(D / 128, (n + 127) / 128);
    gemm_nt<128, 128, 8, 8><<<gk, 256>>>(x_qk, Wk, bk, pk, n, D, D, nullptr);
    gemm_nt<128, 128, 8, 8><<<gk, 256>>>(x_v, Wv, bv, pv, n, D, D, nullptr);

    dim3 gq(D / 64, (f + 63) / 64);
    gemm_nt<64, 64, 4, 4><<<gq, 256>>>(x_qk, Wq, bq, pq, f, D, D, pidx);

    attn_kernel<<<f, NH * 32>>>(pq, pk, pv, pidx, pnp, prank, pctx, n);
    split_attn_kernel<<<NSPLIT, NH * 32>>>(pq, pk, pv, pelist, pne, pml, pacc, n);
    reduce_attn_kernel<<<dim3(MAXE, NH), DH>>>(pelist, pne, pml, pacc, pctx);

    gemm_nt<64, 64, 4, 4><<<gq, 256>>>(pctx, Wo, bo, (float*)d_out, f, D, D, nullptr);
}

// round 3
// speedup vs baseline: 10.7206x; 1.5190x over previous
#include <cuda_runtime.h>
#include <cuda_bf16.h>
#include <math.h>

#define D 768
#define NH 12
#define DH 64
#define NMAX 8192
#define MAXE 64
#define NSPLIT 64

// scratch (device globals; no allocation allowed)
__device__ float g_k[NMAX * D];
__device__ float g_v[NMAX * D];
__device__ float g_q[NMAX * D];
__device__ float g_ctx[NMAX * D];
__device__ int g_idx[NMAX + 1];
__device__ unsigned char g_npad[NMAX];
__device__ int g_rank[NMAX];
__device__ int g_elist[MAXE];
__device__ int g_ne[1];
__device__ float g_part_ml[MAXE * NH * NSPLIT * 2];
__device__ float g_part_acc[MAXE * NH * NSPLIT * DH];

// ---------------------------------------------------------------------------
__global__ void padmask_kernel(const int* __restrict__ ids_raw, int n,
                               const int* __restrict__ padp,
                               unsigned char* __restrict__ npad) {
    int p = blockIdx.x * blockDim.x + threadIdx.x;
    if (p >= n) return;
    int pad = padp[0];
    bool is64 = (n > 1) && (ids_raw[1] == 0);
    long long v = is64 ? ((const long long*)ids_raw)[p] : (long long)ids_raw[p];
    npad[p] = (v != (long long)pad) ? 1 : 0;
}

// ---------------------------------------------------------------------------
__global__ void scan_kernel(const int* __restrict__ qm, int n, int f,
                            int* __restrict__ idxout, int* __restrict__ ne) {
    __shared__ int cnts[256];
    __shared__ int pre[257];
    int t = threadIdx.x;
    int per = (n + 255) / 256;
    int s = t * per;
    int e = s + per; if (e > n) e = n;
    int c = 0;
    for (int p = s; p < e; p++) c += (qm[p] != 0);
    cnts[t] = c;
    __syncthreads();
    if (t == 0) {
        pre[0] = 0;
        for (int i = 0; i < 256; i++) pre[i + 1] = pre[i] + cnts[i];
        ne[0] = 0;
    }
    __syncthreads();
    int rank = pre[t];
    for (int p = s; p < e; p++)
        if (qm[p] != 0) idxout[rank++] = p;
    if (t == 0) idxout[f] = n;
}

// ---------------------------------------------------------------------------
__global__ void flag_empty_kernel(const int* __restrict__ idxarr,
                                  const unsigned char* __restrict__ npad, int f,
                                  int* __restrict__ rank, int* __restrict__ elist,
                                  int* __restrict__ ne) {
    int i = blockIdx.x * blockDim.x + threadIdx.x;
    if (i >= f) return;
    int L = idxarr[i], R = idxarr[i + 1];
    bool any = false;
    for (int p = L; p < R; p++) { if (npad[p]) { any = true; break; } }
    if (any) { rank[i] = -1; return; }
    int r = atomicAdd(ne, 1);
    rank[i] = r;
    if (r < MAXE) elist[r] = i;
}

// ---------------------------------------------------------------------------
// Tensor-core NT GEMM: C[M,N] = A[M,K] @ B[N,K]^T + bias
// bf16 3-term split (Ahi*Bhi + Ahi*Blo + Alo*Bhi) for ~1e-5 accuracy.
// mma.sync.m16n8k16. 8 warps (2 m x 4 n). BN=128, BK=32, BM templated.
// ---------------------------------------------------------------------------
__device__ __forceinline__ void mma_bf16(float* d, const unsigned* a, const unsigned* b) {
    asm volatile(
        "mma.sync.aligned.m16n8k16.row.col.f32.bf16.bf16.f32 "
        "{%0,%1,%2,%3}, {%4,%5,%6,%7}, {%8,%9}, {%0,%1,%2,%3};\n"
        : "+f"(d[0]), "+f"(d[1]), "+f"(d[2]), "+f"(d[3])
        : "r"(a[0]), "r"(a[1]), "r"(a[2]), "r"(a[3]), "r"(b[0]), "r"(b[1]));
}

__device__ __forceinline__ unsigned pack2(__nv_bfloat16 x, __nv_bfloat16 y) {
    __nv_bfloat162 t = __halves2bfloat162(x, y);
    return *reinterpret_cast<unsigned*>(&t);
}

#define BK 32
#define STRIDE 40  // bf16 elements per smem row (BK + 8 pad)

template <int BM>
__global__ __launch_bounds__(256)
void gemm_mma(const float* __restrict__ A, const float* __restrict__ B,
              const float* __restrict__ bias, float* __restrict__ C,
              int M, int N, int K, const int* __restrict__ rowmap) {
    const int BN = 128;
    const int WM = BM / 2;       // warp m extent
    const int MT = WM / 16;      // m16 tiles per warp
    __shared__ __nv_bfloat16 As_hi[BM * STRIDE];
    __shared__ __nv_bfloat16 As_lo[BM * STRIDE];
    __shared__ __nv_bfloat16 Bs_hi[BN * STRIDE];
    __shared__ __nv_bfloat16 Bs_lo[BN * STRIDE];

    int tid = threadIdx.x;
    int warp = tid >> 5;
    int lane = tid & 31;
    int g = lane >> 2;           // group id 0..7
    int tig = lane & 3;          // thread in group
    int wm = warp >> 2;          // 0..1
    int wn = warp & 3;           // 0..3
    int m0 = blockIdx.y * BM;
    int n0 = blockIdx.x * BN;

    float acc[MT][4][4];
#pragma unroll
    for (int i = 0; i < MT; i++)
#pragma unroll
        for (int j = 0; j < 4; j++)
#pragma unroll
            for (int r = 0; r < 4; r++) acc[i][j][r] = 0.f;

    for (int k0 = 0; k0 < K; k0 += BK) {
        // ---- load + split A tile: BM x BK fp32 -> bf16 hi/lo
#pragma unroll
        for (int i = tid; i < BM * (BK / 4); i += 256) {
            int r = i >> 3;            // BK/4 == 8
            int c4 = (i & 7) * 4;
            float4 val = make_float4(0.f, 0.f, 0.f, 0.f);
            int gr = m0 + r;
            if (gr < M) {
                int ar = rowmap ? rowmap[gr] : gr;
                val = *(const float4*)(A + (size_t)ar * K + k0 + c4);
            }
            __nv_bfloat16 h0 = __float2bfloat16_rn(val.x);
            __nv_bfloat16 h1 = __float2bfloat16_rn(val.y);
            __nv_bfloat16 h2 = __float2bfloat16_rn(val.z);
            __nv_bfloat16 h3 = __float2bfloat16_rn(val.w);
            __nv_bfloat16 l0 = __float2bfloat16_rn(val.x - __bfloat162float(h0));
            __nv_bfloat16 l1 = __float2bfloat16_rn(val.y - __bfloat162float(h1));
            __nv_bfloat16 l2 = __float2bfloat16_rn(val.z - __bfloat162float(h2));
            __nv_bfloat16 l3 = __float2bfloat16_rn(val.w - __bfloat162float(h3));
            int o = r * STRIDE + c4;
            *(unsigned*)&As_hi[o] = pack2(h0, h1);
            *(unsigned*)&As_hi[o + 2] = pack2(h2, h3);
            *(unsigned*)&As_lo[o] = pack2(l0, l1);
            *(unsigned*)&As_lo[o + 2] = pack2(l2, l3);
        }
        // ---- load + split B tile: BN x BK
#pragma unroll
        for (int i = tid; i < BN * (BK / 4); i += 256) {
            int r = i >> 3;
            int c4 = (i & 7) * 4;
            float4 val = make_float4(0.f, 0.f, 0.f, 0.f);
            int gr = n0 + r;
            if (gr < N) val = *(const float4*)(B + (size_t)gr * K + k0 + c4);
            __nv_bfloat16 h0 = __float2bfloat16_rn(val.x);
            __nv_bfloat16 h1 = __float2bfloat16_rn(val.y);
            __nv_bfloat16 h2 = __float2bfloat16_rn(val.z);
            __nv_bfloat16 h3 = __float2bfloat16_rn(val.w);
            __nv_bfloat16 l0 = __float2bfloat16_rn(val.x - __bfloat162float(h0));
            __nv_bfloat16 l1 = __float2bfloat16_rn(val.y - __bfloat162float(h1));
            __nv_bfloat16 l2 = __float2bfloat16_rn(val.z - __bfloat162float(h2));
            __nv_bfloat16 l3 = __float2bfloat16_rn(val.w - __bfloat162float(h3));
            int o = r * STRIDE + c4;
            *(unsigned*)&Bs_hi[o] = pack2(h0, h1);
            *(unsigned*)&Bs_hi[o + 2] = pack2(h2, h3);
            *(unsigned*)&Bs_lo[o] = pack2(l0, l1);
            *(unsigned*)&Bs_lo[o + 2] = pack2(l2, l3);
        }
        __syncthreads();

#pragma unroll
        for (int ks = 0; ks < 2; ks++) {  // two k16 steps per BK=32
            unsigned bh[4][2], bl[4][2];
#pragma unroll
            for (int nt = 0; nt < 4; nt++) {
                int off = (wn * 32 + nt * 8 + g) * STRIDE + ks * 16 + 2 * tig;
                bh[nt][0] = *(const unsigned*)&Bs_hi[off];
                bh[nt][1] = *(const unsigned*)&Bs_hi[off + 8];
                bl[nt][0] = *(const unsigned*)&Bs_lo[off];
                bl[nt][1] = *(const unsigned*)&Bs_lo[off + 8];
            }
#pragma unroll
            for (int mt = 0; mt < MT; mt++) {
                int off = (wm * WM + mt * 16 + g) * STRIDE + ks * 16 + 2 * tig;
                unsigned ah[4], al[4];
                ah[0] = *(const unsigned*)&As_hi[off];
                ah[1] = *(const unsigned*)&As_hi[off + 8 * STRIDE];
                ah[2] = *(const unsigned*)&As_hi[off + 8];
                ah[3] = *(const unsigned*)&As_hi[off + 8 * STRIDE + 8];
                al[0] = *(const unsigned*)&As_lo[off];
                al[1] = *(const unsigned*)&As_lo[off + 8 * STRIDE];
                al[2] = *(const unsigned*)&As_lo[off + 8];
                al[3] = *(const unsigned*)&As_lo[off + 8 * STRIDE + 8];
#pragma unroll
                for (int nt = 0; nt < 4; nt++) {
                    mma_bf16(acc[mt][nt], ah, bh[nt]);
                    mma_bf16(acc[mt][nt], ah, bl[nt]);
                    mma_bf16(acc[mt][nt], al, bh[nt]);
                }
            }
        }
        __syncthreads();
    }

    // ---- epilogue: add bias, store
#pragma unroll
    for (int mt = 0; mt < MT; mt++) {
#pragma unroll
        for (int nt = 0; nt < 4; nt++) {
            int row = m0 + wm * WM + mt * 16 + g;
            int col = n0 + wn * 32 + nt * 8 + 2 * tig;
            float b0 = bias[col], b1 = bias[col + 1];
            if (row < M) {
                float2 o = make_float2(acc[mt][nt][0] + b0, acc[mt][nt][1] + b1);
                *(float2*)(C + (size_t)row * N + col) = o;
            }
            if (row + 8 < M) {
                float2 o = make_float2(acc[mt][nt][2] + b0, acc[mt][nt][3] + b1);
                *(float2*)(C + (size_t)(row + 8) * N + col) = o;
            }
        }
    }
}

// ---------------------------------------------------------------------------
// normal attention: one block per feature, one warp per head
// ---------------------------------------------------------------------------
__global__ __launch_bounds__(NH * 32)
void attn_kernel(const float* __restrict__ q, const float* __restrict__ k,
                 const float* __restrict__ v, const int* __restrict__ idxarr,
                 const unsigned char* __restrict__ npad,
                 const int* __restrict__ rankarr,
                 float* __restrict__ ctx, int n) {
    int i = blockIdx.x;
    int rk = rankarr[i];
    if (rk >= 0 && rk < MAXE) return;  // split path
    int h = threadIdx.x / 32;
    int lane = threadIdx.x % 32;

    __shared__ float qsh[NH][DH];
    const float* qb = q + (size_t)i * D + h * DH;
    qsh[h][lane] = qb[lane];
    qsh[h][lane + 32] = qb[lane + 32];
    __syncwarp();

    int left = idxarr[i];
    int right = idxarr[i + 1];
    float q0 = qsh[h][lane];
    float q1 = qsh[h][lane + 32];
    const float scale = 0.125f;

    float m = -1e30f;
    int cnt = 0;
    for (int p = left; p < right; p++) {
        if (!npad[p]) continue;
        const float* kb = k + (size_t)p * D + h * DH;
        float part = q0 * kb[lane] + q1 * kb[lane + 32];
#pragma unroll
        for (int o = 16; o > 0; o >>= 1) part += __shfl_xor_sync(0xffffffffu, part, o);
        float s = part * scale;
        cnt++;
        if (s > m) m = s;
    }

    if (cnt > 0) {
        float l = 0.f, a0 = 0.f, a1 = 0.f;
        for (int p = left; p < right; p++) {
            if (!npad[p]) continue;
            const float* kb = k + (size_t)p * D + h * DH;
            float part = q0 * kb[lane] + q1 * kb[lane + 32];
#pragma unroll
            for (int o = 16; o > 0; o >>= 1) part += __shfl_xor_sync(0xffffffffu, part, o);
            float e = expf(part * scale - m);
            const float* vb = v + (size_t)p * D + h * DH;
            l += e;
            a0 += e * vb[lane];
            a1 += e * vb[lane + 32];
        }
        ctx[(size_t)i * D + h * DH + lane] = a0 / l;
        ctx[(size_t)i * D + h * DH + lane + 32] = a1 / l;
    } else {
        float m_i = -1e30f, l_i = 0.f;
        float acc[DH];
#pragma unroll
        for (int d = 0; d < DH; d++) acc[d] = 0.f;
        for (int p = lane; p < n; p += 32) {
            const float* kb = k + (size_t)p * D + h * DH;
            float s = 0.f;
#pragma unroll
            for (int d = 0; d < DH; d++) s += qsh[h][d] * kb[d];
            s *= scale;
            if (s > m_i) {
                float c = expf(m_i - s);
                l_i *= c;
#pragma unroll
                for (int d = 0; d < DH; d++) acc[d] *= c;
                m_i = s;
            }
            float e = expf(s - m_i);
            const float* vb = v + (size_t)p * D + h * DH;
            l_i += e;
#pragma unroll
            for (int d = 0; d < DH; d++) acc[d] += e * vb[d];
        }
        float M_ = m_i;
#pragma unroll
        for (int o = 16; o > 0; o >>= 1) M_ = fmaxf(M_, __shfl_xor_sync(0xffffffffu, M_, o));
        float c = expf(m_i - M_);
        float lt = l_i * c;
#pragma unroll
        for (int o = 16; o > 0; o >>= 1) lt += __shfl_xor_sync(0xffffffffu, lt, o);
#pragma unroll
        for (int d = 0; d < DH; d++) {
            float vs = acc[d] * c;
#pragma unroll
            for (int o = 16; o > 0; o >>= 1) vs += __shfl_xor_sync(0xffffffffu, vs, o);
            if (lane == 0) ctx[(size_t)i * D + h * DH + d] = vs / lt;
        }
    }
}

// ---------------------------------------------------------------------------
// split-K flash decode for fully-masked features
// ---------------------------------------------------------------------------
__global__ __launch_bounds__(NH * 32)
void split_attn_kernel(const float* __restrict__ q, const float* __restrict__ k,
                       const float* __restrict__ v, const int* __restrict__ elist,
                       const int* __restrict__ nep,
                       float* __restrict__ part_ml, float* __restrict__ part_acc,
                       int n) {
    int split = blockIdx.x;
    int h = threadIdx.x / 32;
    int lane = threadIdx.x % 32;
    int ne = nep[0];
    if (ne > MAXE) ne = MAXE;
    if (ne == 0) return;
    int chunk = (n + NSPLIT - 1) / NSPLIT;
    int ks = split * chunk;
    int ke = ks + chunk; if (ke > n) ke = n;
    const float scale = 0.125f;

    for (int e0 = 0; e0 < ne; e0 += 8) {
        int gs = ne - e0; if (gs > 8) gs = 8;
        float q0[8], q1[8], m_[8], l_[8], a0[8], a1[8];
#pragma unroll
        for (int j = 0; j < 8; j++) {
            if (j < gs) {
                int ft = elist[e0 + j];
                q0[j] = q[(size_t)ft * D + h * DH + lane];
                q1[j] = q[(size_t)ft * D + h * DH + lane + 32];
            } else { q0[j] = 0.f; q1[j] = 0.f; }
            m_[j] = -1e30f; l_[j] = 0.f; a0[j] = 0.f; a1[j] = 0.f;
        }
        for (int p = ks; p < ke; p++) {
            const float* kb = k + (size_t)p * D + h * DH;
            const float* vb = v + (size_t)p * D + h * DH;
            float k0 = kb[lane], k1 = kb[lane + 32];
            float v0 = vb[lane], v1 = vb[lane + 32];
            float s[8];
#pragma unroll
            for (int j = 0; j < 8; j++) s[j] = q0[j] * k0 + q1[j] * k1;
#pragma unroll
            for (int o = 16; o > 0; o >>= 1)
#pragma unroll
                for (int j = 0; j < 8; j++) s[j] += __shfl_xor_sync(0xffffffffu, s[j], o);
#pragma unroll
            for (int j = 0; j < 8; j++) {
                float sc = s[j] * scale;
                float mn = fmaxf(m_[j], sc);
                float corr = expf(m_[j] - mn);
                float e = expf(sc - mn);
                l_[j] = l_[j] * corr + e;
                a0[j] = a0[j] * corr + e * v0;
                a1[j] = a1[j] * corr + e * v1;
                m_[j] = mn;
            }
        }
#pragma unroll
        for (int j = 0; j < 8; j++) {
            if (j >= gs) continue;
            size_t base = ((size_t)(e0 + j) * NH + h) * NSPLIT + split;
            if (lane == 0) { part_ml[base * 2] = m_[j]; part_ml[base * 2 + 1] = l_[j]; }
            part_acc[base * DH + lane] = a0[j];
            part_acc[base * DH + lane + 32] = a1[j];
        }
    }
}

__global__ __launch_bounds__(DH)
void reduce_attn_kernel(const int* __restrict__ elist, const int* __restrict__ nep,
                        const float* __restrict__ part_ml,
                        const float* __restrict__ part_acc,
                        float* __restrict__ ctx) {
    int e = blockIdx.x, h = blockIdx.y;
    int ne = nep[0]; if (ne > MAXE) ne = MAXE;
    if (e >= ne) return;
    int d = threadIdx.x;
    __shared__ float wsh[NSPLIT];
    __shared__ float Lsh;
    if (d == 0) {
        float M = -1e30f;
        size_t mb = ((size_t)e * NH + h) * NSPLIT;
        for (int s = 0; s < NSPLIT; s++) {
            float m = part_ml[(mb + s) * 2];
            if (m > M) M = m;
        }
        float L = 0.f;
        for (int s = 0; s < NSPLIT; s++) {
            float m = part_ml[(mb + s) * 2];
            float l = part_ml[(mb + s) * 2 + 1];
            float w = expf(m - M);
            wsh[s] = w;
            L += w * l;
        }
        Lsh = L;
    }
    __syncthreads();
    float acc = 0.f;
    size_t ab = ((size_t)e * NH + h) * NSPLIT;
    for (int s = 0; s < NSPLIT; s++) acc += wsh[s] * part_acc[(ab + s) * DH + d];
    int ft = elist[e];
    ctx[(size_t)ft * D + h * DH + d] = acc / Lsh;
}

// ---------------------------------------------------------------------------
extern "C" void kernel_launch(void* const* d_in, const int* in_sizes, int n_in,
                              void* d_out, int out_size) {
    const float* x_qk = (const float*)d_in[0];
    const float* x_v = (const float*)d_in[1];
    const int* qm = (const int*)d_in[2];
    const int* ids = (const int*)d_in[3];
    const int* padp = (const int*)d_in[4];
    const float* Wq = (const float*)d_in[5];
    const float* bq = (const float*)d_in[6];
    const float* Wk = (const float*)d_in[7];
    const float* bk = (const float*)d_in[8];
    const float* Wv = (const float*)d_in[9];
    const float* bv = (const float*)d_in[10];
    const float* Wo = (const float*)d_in[11];
    const float* bo = (const float*)d_in[12];

    int n = in_sizes[0] / D;
    int f = out_size / D;

    float *pk, *pv, *pq, *pctx, *pml, *pacc;
    int *pidx, *prank, *pelist, *pne;
    unsigned char* pnp;
    cudaGetSymbolAddress((void**)&pk, g_k);
    cudaGetSymbolAddress((void**)&pv, g_v);
    cudaGetSymbolAddress((void**)&pq, g_q);
    cudaGetSymbolAddress((void**)&pctx, g_ctx);
    cudaGetSymbolAddress((void**)&pidx, g_idx);
    cudaGetSymbolAddress((void**)&pnp, g_npad);
    cudaGetSymbolAddress((void**)&prank, g_rank);
    cudaGetSymbolAddress((void**)&pelist, g_elist);
    cudaGetSymbolAddress((void**)&pne, g_ne);
    cudaGetSymbolAddress((void**)&pml, g_part_ml);
    cudaGetSymbolAddress((void**)&pacc, g_part_acc);

    padmask_kernel<<<(n + 255) / 256, 256>>>(ids, n, padp, pnp);
    scan_kernel<<<1, 256>>>(qm, n, f, pidx, pne);
    flag_empty_kernel<<<(f + 255) / 256, 256>>>(pidx, pnp, f, prank, pelist, pne);

    dim3 gk(D / 128, (n + 127) / 128);
    gemm_mma<128><<<gk, 256>>>(x_qk, Wk, bk, pk, n, D, D, nullptr);
    gemm_mma<128><<<gk, 256>>>(x_v, Wv, bv, pv, n, D, D, nullptr);

    dim3 gq(D / 128, (f + 63) / 64);
    gemm_mma<64><<<gq, 256>>>(x_qk, Wq, bq, pq, f, D, D, pidx);

    attn_kernel<<<f, NH * 32>>>(pq, pk, pv, pidx, pnp, prank, pctx, n);
    split_attn_kernel<<<NSPLIT, NH * 32>>>(pq, pk, pv, pelist, pne, pml, pacc, n);
    reduce_attn_kernel<<<dim3(MAXE, NH), DH>>>(pelist, pne, pml, pacc, pctx);

    gemm_mma<64><<<gq, 256>>>(pctx, Wo, bo, (float*)d_out, f, D, D, nullptr);
}

// round 5
// speedup vs baseline: 12.2500x; 1.1427x over previous
#include <cuda_runtime.h>
#include <cuda_bf16.h>
#include <math.h>
#include <stdint.h>

#define D 768
#define NH 12
#define DH 64
#define NMAX 8192
#define MAXE 64
#define NSPLIT 64
#define STRIDE 40  // bf16 elems per smem row (32 + 8 pad)

// fp32 scratch
__device__ float g_k[NMAX * D];
__device__ float g_v[NMAX * D];
__device__ float g_q[NMAX * D];
__device__ float g_ctx[NMAX * D];
__device__ int g_idx[NMAX + 1];
__device__ unsigned char g_npad[NMAX];
__device__ int g_rank[NMAX];
__device__ int g_elist[MAXE];
__device__ int g_ne[1];
__device__ float g_part_ml[MAXE * NH * NSPLIT * 2];
__device__ float g_part_acc[MAXE * NH * NSPLIT * DH];

// bf16 hi/lo pre-split scratch
__device__ __nv_bfloat16 g_xqk_h[NMAX * D], g_xqk_l[NMAX * D];
__device__ __nv_bfloat16 g_xv_h[NMAX * D], g_xv_l[NMAX * D];
__device__ __nv_bfloat16 g_ctx_h[NMAX * D], g_ctx_l[NMAX * D];
__device__ __nv_bfloat16 g_wk_h[D * D], g_wk_l[D * D];
__device__ __nv_bfloat16 g_wv_h[D * D], g_wv_l[D * D];
__device__ __nv_bfloat16 g_wq_h[D * D], g_wq_l[D * D];
__device__ __nv_bfloat16 g_wo_h[D * D], g_wo_l[D * D];

// ---------------------------------------------------------------------------
__device__ __forceinline__ unsigned pack2(__nv_bfloat16 x, __nv_bfloat16 y) {
    __nv_bfloat162 t = __halves2bfloat162(x, y);
    return *reinterpret_cast<unsigned*>(&t);
}

// fp32 -> bf16 hi/lo split, vectorized
__global__ void split_kernel(const float4* __restrict__ src, uint2* __restrict__ hi,
                             uint2* __restrict__ lo, int n4) {
    int i = blockIdx.x * blockDim.x + threadIdx.x;
    if (i >= n4) return;
    float4 v = src[i];
    __nv_bfloat16 h0 = __float2bfloat16_rn(v.x);
    __nv_bfloat16 h1 = __float2bfloat16_rn(v.y);
    __nv_bfloat16 h2 = __float2bfloat16_rn(v.z);
    __nv_bfloat16 h3 = __float2bfloat16_rn(v.w);
    __nv_bfloat16 l0 = __float2bfloat16_rn(v.x - __bfloat162float(h0));
    __nv_bfloat16 l1 = __float2bfloat16_rn(v.y - __bfloat162float(h1));
    __nv_bfloat16 l2 = __float2bfloat16_rn(v.z - __bfloat162float(h2));
    __nv_bfloat16 l3 = __float2bfloat16_rn(v.w - __bfloat162float(h3));
    hi[i] = make_uint2(pack2(h0, h1), pack2(h2, h3));
    lo[i] = make_uint2(pack2(l0, l1), pack2(l2, l3));
}

// ---------------------------------------------------------------------------
__global__ void padmask_kernel(const int* __restrict__ ids_raw, int n,
                               const int* __restrict__ padp,
                               unsigned char* __restrict__ npad) {
    int p = blockIdx.x * blockDim.x + threadIdx.x;
    if (p >= n) return;
    int pad = padp[0];
    bool is64 = (n > 1) && (ids_raw[1] == 0);
    long long v = is64 ? ((const long long*)ids_raw)[p] : (long long)ids_raw[p];
    npad[p] = (v != (long long)pad) ? 1 : 0;
}

// ---------------------------------------------------------------------------
__global__ void scan_kernel(const int* __restrict__ qm, int n, int f,
                            int* __restrict__ idxout, int* __restrict__ ne) {
    __shared__ int cnts[256];
    __shared__ int pre[257];
    int t = threadIdx.x;
    int per = (n + 255) / 256;
    int s = t * per;
    int e = s + per; if (e > n) e = n;
    int c = 0;
    for (int p = s; p < e; p++) c += (qm[p] != 0);
    cnts[t] = c;
    __syncthreads();
    if (t == 0) {
        pre[0] = 0;
        for (int i = 0; i < 256; i++) pre[i + 1] = pre[i] + cnts[i];
        ne[0] = 0;
    }
    __syncthreads();
    int rank = pre[t];
    for (int p = s; p < e; p++)
        if (qm[p] != 0) idxout[rank++] = p;
    if (t == 0) idxout[f] = n;
}

// ---------------------------------------------------------------------------
__global__ void flag_empty_kernel(const int* __restrict__ idxarr,
                                  const unsigned char* __restrict__ npad, int f,
                                  int* __restrict__ rank, int* __restrict__ elist,
                                  int* __restrict__ ne) {
    int i = blockIdx.x * blockDim.x + threadIdx.x;
    if (i >= f) return;
    int L = idxarr[i], R = idxarr[i + 1];
    bool any = false;
    for (int p = L; p < R; p++) { if (npad[p]) { any = true; break; } }
    if (any) { rank[i] = -1; return; }
    int r = atomicAdd(ne, 1);
    rank[i] = r;
    if (r < MAXE) elist[r] = i;
}

// ---------------------------------------------------------------------------
// Tensor-core NT GEMM on pre-split bf16 hi/lo operands.
// C[M,N] = A @ B^T + bias, 3-term (AhBh + AhBl + AlBh).
// 8 warps (2m x 4n), mma.m16n8k16, BK=32, BN=128, BM templated.
// cp.async double-buffered (2 stages). gridDim.z selects arg set (fused K/V).
// ---------------------------------------------------------------------------
struct GArg {
    const __nv_bfloat16 *Ah, *Al, *Bh, *Bl;
    const float* bias;
    float* C;
};

__device__ __forceinline__ void mma_bf16(float* d, const unsigned* a, const unsigned* b) {
    asm volatile(
        "mma.sync.aligned.m16n8k16.row.col.f32.bf16.bf16.f32 "
        "{%0,%1,%2,%3}, {%4,%5,%6,%7}, {%8,%9}, {%0,%1,%2,%3};\n"
        : "+f"(d[0]), "+f"(d[1]), "+f"(d[2]), "+f"(d[3])
        : "r"(a[0]), "r"(a[1]), "r"(a[2]), "r"(a[3]), "r"(b[0]), "r"(b[1]));
}

__device__ __forceinline__ void cp_async16(__nv_bfloat16* dst, const __nv_bfloat16* src) {
    unsigned s = (unsigned)__cvta_generic_to_shared(dst);
    asm volatile("cp.async.cg.shared.global [%0], [%1], 16;\n" :: "r"(s), "l"(src));
}

template <int BM>
__global__ __launch_bounds__(256)
void gemm_mma_bf(GArg g0, GArg g1, int M, int N, int K, const int* __restrict__ rowmap) {
    const int WM = BM / 2;
    const int MT = WM / 16;
    const int ASZ = BM * STRIDE;
    const int BSZ = 128 * STRIDE;
    const int STG = 2 * ASZ + 2 * BSZ;
    extern __shared__ __nv_bfloat16 smraw[];

    GArg G = (blockIdx.z == 0) ? g0 : g1;

    int tid = threadIdx.x;
    int warp = tid >> 5;
    int lane = tid & 31;
    int g = lane >> 2;
    int tig = lane & 3;
    int wm = warp >> 2;
    int wn = warp & 3;
    int m0 = blockIdx.y * BM;
    int n0 = blockIdx.x * 128;

    float acc[MT][4][4];
#pragma unroll
    for (int i = 0; i < MT; i++)
#pragma unroll
        for (int j = 0; j < 4; j++)
#pragma unroll
            for (int r = 0; r < 4; r++) acc[i][j][r] = 0.f;

    // ---- stage loader: each row needs BK=32 bf16 = 4 x 16B chunks
    auto load_stage = [&](int st, int k0) {
        __nv_bfloat16* base = smraw + st * STG;
#pragma unroll
        for (int c = tid; c < BM * 4; c += 256) {
            int r = c >> 2, ch = c & 3;
            int gr = m0 + r;
            if (gr >= M) gr = M - 1;  // clamp: junk rows discarded at epilogue
            int ar = rowmap ? rowmap[gr] : gr;
            size_t go = (size_t)ar * K + k0 + ch * 8;
            int dst = r * STRIDE + ch * 8;
            cp_async16(base + dst, G.Ah + go);
            cp_async16(base + ASZ + dst, G.Al + go);
        }
#pragma unroll
        for (int c = tid; c < 128 * 4; c += 256) {
            int r = c >> 2, ch = c & 3;
            size_t go = (size_t)(n0 + r) * K + k0 + ch * 8;
            int dst = r * STRIDE + ch * 8;
            cp_async16(base + 2 * ASZ + dst, G.Bh + go);
            cp_async16(base + 2 * ASZ + BSZ + dst, G.Bl + go);
        }
        asm volatile("cp.async.commit_group;\n");
    };

    int nk = K / 32;
    load_stage(0, 0);

    for (int i = 0; i < nk; i++) {
        if (i + 1 < nk) {
            load_stage((i + 1) & 1, (i + 1) * 32);
            asm volatile("cp.async.wait_group 1;\n");
        } else {
            asm volatile("cp.async.wait_group 0;\n");
        }
        __syncthreads();

        const __nv_bfloat16* base = smraw + (i & 1) * STG;
        const __nv_bfloat16* sAh = base;
        const __nv_bfloat16* sAl = base + ASZ;
        const __nv_bfloat16* sBh = base + 2 * ASZ;
        const __nv_bfloat16* sBl = base + 2 * ASZ + BSZ;

#pragma unroll
        for (int ks = 0; ks < 2; ks++) {
            unsigned bh[4][2], bl[4][2];
#pragma unroll
            for (int nt = 0; nt < 4; nt++) {
                int off = (wn * 32 + nt * 8 + g) * STRIDE + ks * 16 + 2 * tig;
                bh[nt][0] = *(const unsigned*)&sBh[off];
                bh[nt][1] = *(const unsigned*)&sBh[off + 8];
                bl[nt][0] = *(const unsigned*)&sBl[off];
                bl[nt][1] = *(const unsigned*)&sBl[off + 8];
            }
#pragma unroll
            for (int mt = 0; mt < MT; mt++) {
                int off = (wm * WM + mt * 16 + g) * STRIDE + ks * 16 + 2 * tig;
                unsigned ah[4], al[4];
                ah[0] = *(const unsigned*)&sAh[off];
                ah[1] = *(const unsigned*)&sAh[off + 8 * STRIDE];
                ah[2] = *(const unsigned*)&sAh[off + 8];
                ah[3] = *(const unsigned*)&sAh[off + 8 * STRIDE + 8];
                al[0] = *(const unsigned*)&sAl[off];
                al[1] = *(const unsigned*)&sAl[off + 8 * STRIDE];
                al[2] = *(const unsigned*)&sAl[off + 8];
                al[3] = *(const unsigned*)&sAl[off + 8 * STRIDE + 8];
#pragma unroll
                for (int nt = 0; nt < 4; nt++) {
                    mma_bf16(acc[mt][nt], ah, bh[nt]);
                    mma_bf16(acc[mt][nt], ah, bl[nt]);
                    mma_bf16(acc[mt][nt], al, bh[nt]);
                }
            }
        }
        __syncthreads();
    }

    // ---- epilogue
#pragma unroll
    for (int mt = 0; mt < MT; mt++) {
#pragma unroll
        for (int nt = 0; nt < 4; nt++) {
            int row = m0 + wm * WM + mt * 16 + g;
            int col = n0 + wn * 32 + nt * 8 + 2 * tig;
            float b0 = G.bias[col], b1 = G.bias[col + 1];
            if (row < M) {
                float2 o = make_float2(acc[mt][nt][0] + b0, acc[mt][nt][1] + b1);
                *(float2*)(G.C + (size_t)row * N + col) = o;
            }
            if (row + 8 < M) {
                float2 o = make_float2(acc[mt][nt][2] + b0, acc[mt][nt][3] + b1);
                *(float2*)(G.C + (size_t)(row + 8) * N + col) = o;
            }
        }
    }
}

// ---------------------------------------------------------------------------
// normal attention: one block per feature, one warp per head
// ---------------------------------------------------------------------------
__global__ __launch_bounds__(NH * 32)
void attn_kernel(const float* __restrict__ q, const float* __restrict__ k,
                 const float* __restrict__ v, const int* __restrict__ idxarr,
                 const unsigned char* __restrict__ npad,
                 const int* __restrict__ rankarr,
                 float* __restrict__ ctx, int n) {
    int i = blockIdx.x;
    int rk = rankarr[i];
    if (rk >= 0 && rk < MAXE) return;  // split path
    int h = threadIdx.x / 32;
    int lane = threadIdx.x % 32;

    __shared__ float qsh[NH][DH];
    const float* qb = q + (size_t)i * D + h * DH;
    qsh[h][lane] = qb[lane];
    qsh[h][lane + 32] = qb[lane + 32];
    __syncwarp();

    int left = idxarr[i];
    int right = idxarr[i + 1];
    float q0 = qsh[h][lane];
    float q1 = qsh[h][lane + 32];
    const float scale = 0.125f;

    float m = -1e30f;
    int cnt = 0;
    for (int p = left; p < right; p++) {
        if (!npad[p]) continue;
        const float* kb = k + (size_t)p * D + h * DH;
        float part = q0 * kb[lane] + q1 * kb[lane + 32];
#pragma unroll
        for (int o = 16; o > 0; o >>= 1) part += __shfl_xor_sync(0xffffffffu, part, o);
        float s = part * scale;
        cnt++;
        if (s > m) m = s;
    }

    if (cnt > 0) {
        float l = 0.f, a0 = 0.f, a1 = 0.f;
        for (int p = left; p < right; p++) {
            if (!npad[p]) continue;
            const float* kb = k + (size_t)p * D + h * DH;
            float part = q0 * kb[lane] + q1 * kb[lane + 32];
#pragma unroll
            for (int o = 16; o > 0; o >>= 1) part += __shfl_xor_sync(0xffffffffu, part, o);
            float e = expf(part * scale - m);
            const float* vb = v + (size_t)p * D + h * DH;
            l += e;
            a0 += e * vb[lane];
            a1 += e * vb[lane + 32];
        }
        ctx[(size_t)i * D + h * DH + lane] = a0 / l;
        ctx[(size_t)i * D + h * DH + lane + 32] = a1 / l;
    } else {
        float m_i = -1e30f, l_i = 0.f;
        float acc[DH];
#pragma unroll
        for (int d = 0; d < DH; d++) acc[d] = 0.f;
        for (int p = lane; p < n; p += 32) {
            const float* kb = k + (size_t)p * D + h * DH;
            float s = 0.f;
#pragma unroll
            for (int d = 0; d < DH; d++) s += qsh[h][d] * kb[d];
            s *= scale;
            if (s > m_i) {
                float c = expf(m_i - s);
                l_i *= c;
#pragma unroll
                for (int d = 0; d < DH; d++) acc[d] *= c;
                m_i = s;
            }
            float e = expf(s - m_i);
            const float* vb = v + (size_t)p * D + h * DH;
            l_i += e;
#pragma unroll
            for (int d = 0; d < DH; d++) acc[d] += e * vb[d];
        }
        float M_ = m_i;
#pragma unroll
        for (int o = 16; o > 0; o >>= 1) M_ = fmaxf(M_, __shfl_xor_sync(0xffffffffu, M_, o));
        float c = expf(m_i - M_);
        float lt = l_i * c;
#pragma unroll
        for (int o = 16; o > 0; o >>= 1) lt += __shfl_xor_sync(0xffffffffu, lt, o);
#pragma unroll
        for (int d = 0; d < DH; d++) {
            float vs = acc[d] * c;
#pragma unroll
            for (int o = 16; o > 0; o >>= 1) vs += __shfl_xor_sync(0xffffffffu, vs, o);
            if (lane == 0) ctx[(size_t)i * D + h * DH + d] = vs / lt;
        }
    }
}

// ---------------------------------------------------------------------------
// split-K flash decode for fully-masked features
// ---------------------------------------------------------------------------
__global__ __launch_bounds__(NH * 32)
void split_attn_kernel(const float* __restrict__ q, const float* __restrict__ k,
                       const float* __restrict__ v, const int* __restrict__ elist,
                       const int* __restrict__ nep,
                       float* __restrict__ part_ml, float* __restrict__ part_acc,
                       int n) {
    int split = blockIdx.x;
    int h = threadIdx.x / 32;
    int lane = threadIdx.x % 32;
    int ne = nep[0];
    if (ne > MAXE) ne = MAXE;
    if (ne == 0) return;
    int chunk = (n + NSPLIT - 1) / NSPLIT;
    int ks = split * chunk;
    int ke = ks + chunk; if (ke > n) ke = n;
    const float scale = 0.125f;

    for (int e0 = 0; e0 < ne; e0 += 8) {
        int gs = ne - e0; if (gs > 8) gs = 8;
        float q0[8], q1[8], m_[8], l_[8], a0[8], a1[8];
#pragma unroll
        for (int j = 0; j < 8; j++) {
            if (j < gs) {
                int ft = elist[e0 + j];
                q0[j] = q[(size_t)ft * D + h * DH + lane];
                q1[j] = q[(size_t)ft * D + h * DH + lane + 32];
            } else { q0[j] = 0.f; q1[j] = 0.f; }
            m_[j] = -1e30f; l_[j] = 0.f; a0[j] = 0.f; a1[j] = 0.f;
        }
        for (int p = ks; p < ke; p++) {
            const float* kb = k + (size_t)p * D + h * DH;
            const float* vb = v + (size_t)p * D + h * DH;
            float k0 = kb[lane], k1 = kb[lane + 32];
            float v0 = vb[lane], v1 = vb[lane + 32];
            float s[8];
#pragma unroll
            for (int j = 0; j < 8; j++) s[j] = q0[j] * k0 + q1[j] * k1;
#pragma unroll
            for (int o = 16; o > 0; o >>= 1)
#pragma unroll
                for (int j = 0; j < 8; j++) s[j] += __shfl_xor_sync(0xffffffffu, s[j], o);
#pragma unroll
            for (int j = 0; j < 8; j++) {
                float sc = s[j] * scale;
                float mn = fmaxf(m_[j], sc);
                float corr = expf(m_[j] - mn);
                float e = expf(sc - mn);
                l_[j] = l_[j] * corr + e;
                a0[j] = a0[j] * corr + e * v0;
                a1[j] = a1[j] * corr + e * v1;
                m_[j] = mn;
            }
        }
#pragma unroll
        for (int j = 0; j < 8; j++) {
            if (j >= gs) continue;
            size_t base = ((size_t)(e0 + j) * NH + h) * NSPLIT + split;
            if (lane == 0) { part_ml[base * 2] = m_[j]; part_ml[base * 2 + 1] = l_[j]; }
            part_acc[base * DH + lane] = a0[j];
            part_acc[base * DH + lane + 32] = a1[j];
        }
    }
}

__global__ __launch_bounds__(DH)
void reduce_attn_kernel(const int* __restrict__ elist, const int* __restrict__ nep,
                        const float* __restrict__ part_ml,
                        const float* __restrict__ part_acc,
                        float* __restrict__ ctx) {
    int e = blockIdx.x, h = blockIdx.y;
    int ne = nep[0]; if (ne > MAXE) ne = MAXE;
    if (e >= ne) return;
    int d = threadIdx.x;
    __shared__ float wsh[NSPLIT];
    __shared__ float Lsh;
    if (d == 0) {
        float M = -1e30f;
        size_t mb = ((size_t)e * NH + h) * NSPLIT;
        for (int s = 0; s < NSPLIT; s++) {
            float m = part_ml[(mb + s) * 2];
            if (m > M) M = m;
        }
        float L = 0.f;
        for (int s = 0; s < NSPLIT; s++) {
            float m = part_ml[(mb + s) * 2];
            float l = part_ml[(mb + s) * 2 + 1];
            float w = expf(m - M);
            wsh[s] = w;
            L += w * l;
        }
        Lsh = L;
    }
    __syncthreads();
    float acc = 0.f;
    size_t ab = ((size_t)e * NH + h) * NSPLIT;
    for (int s = 0; s < NSPLIT; s++) acc += wsh[s] * part_acc[(ab + s) * DH + d];
    int ft = elist[e];
    ctx[(size_t)ft * D + h * DH + d] = acc / Lsh;
}

// ---------------------------------------------------------------------------
extern "C" void kernel_launch(void* const* d_in, const int* in_sizes, int n_in,
                              void* d_out, int out_size) {
    const float* x_qk = (const float*)d_in[0];
    const float* x_v = (const float*)d_in[1];
    const int* qm = (const int*)d_in[2];
    const int* ids = (const int*)d_in[3];
    const int* padp = (const int*)d_in[4];
    const float* Wq = (const float*)d_in[5];
    const float* bq = (const float*)d_in[6];
    const float* Wk = (const float*)d_in[7];
    const float* bk = (const float*)d_in[8];
    const float* Wv = (const float*)d_in[9];
    const float* bv = (const float*)d_in[10];
    const float* Wo = (const float*)d_in[11];
    const float* bo = (const float*)d_in[12];

    int n = in_sizes[0] / D;
    int f = out_size / D;

    float *pk, *pv, *pq, *pctx, *pml, *pacc;
    int *pidx, *prank, *pelist, *pne;
    unsigned char* pnp;
    cudaGetSymbolAddress((void**)&pk, g_k);
    cudaGetSymbolAddress((void**)&pv, g_v);
    cudaGetSymbolAddress((void**)&pq, g_q);
    cudaGetSymbolAddress((void**)&pctx, g_ctx);
    cudaGetSymbolAddress((void**)&pidx, g_idx);
    cudaGetSymbolAddress((void**)&pnp, g_npad);
    cudaGetSymbolAddress((void**)&prank, g_rank);
    cudaGetSymbolAddress((void**)&pelist, g_elist);
    cudaGetSymbolAddress((void**)&pne, g_ne);
    cudaGetSymbolAddress((void**)&pml, g_part_ml);
    cudaGetSymbolAddress((void**)&pacc, g_part_acc);

    __nv_bfloat16 *xqk_h, *xqk_l, *xv_h, *xv_l, *ctx_h, *ctx_l;
    __nv_bfloat16 *wk_h, *wk_l, *wv_h, *wv_l, *wq_h, *wq_l, *wo_h, *wo_l;
    cudaGetSymbolAddress((void**)&xqk_h, g_xqk_h);
    cudaGetSymbolAddress((void**)&xqk_l, g_xqk_l);
    cudaGetSymbolAddress((void**)&xv_h, g_xv_h);
    cudaGetSymbolAddress((void**)&xv_l, g_xv_l);
    cudaGetSymbolAddress((void**)&ctx_h, g_ctx_h);
    cudaGetSymbolAddress((void**)&ctx_l, g_ctx_l);
    cudaGetSymbolAddress((void**)&wk_h, g_wk_h);
    cudaGetSymbolAddress((void**)&wk_l, g_wk_l);
    cudaGetSymbolAddress((void**)&wv_h, g_wv_h);
    cudaGetSymbolAddress((void**)&wv_l, g_wv_l);
    cudaGetSymbolAddress((void**)&wq_h, g_wq_h);
    cudaGetSymbolAddress((void**)&wq_l, g_wq_l);
    cudaGetSymbolAddress((void**)&wo_h, g_wo_h);
    cudaGetSymbolAddress((void**)&wo_l, g_wo_l);

    padmask_kernel<<<(n + 255) / 256, 256>>>(ids, n, padp, pnp);
    scan_kernel<<<1, 256>>>(qm, n, f, pidx, pne);
    flag_empty_kernel<<<(f + 255) / 256, 256>>>(pidx, pnp, f, prank, pelist, pne);

    // pre-split inputs + weights to bf16 hi/lo
    int nx4 = n * D / 4;
    int nw4 = D * D / 4;
    split_kernel<<<(nx4 + 255) / 256, 256>>>((const float4*)x_qk, (uint2*)xqk_h, (uint2*)xqk_l, nx4);
    split_kernel<<<(nx4 + 255) / 256, 256>>>((const float4*)x_v, (uint2*)xv_h, (uint2*)xv_l, nx4);
    split_kernel<<<(nw4 + 255) / 256, 256>>>((const float4*)Wk, (uint2*)wk_h, (uint2*)wk_l, nw4);
    split_kernel<<<(nw4 + 255) / 256, 256>>>((const float4*)Wv, (uint2*)wv_h, (uint2*)wv_l, nw4);
    split_kernel<<<(nw4 + 255) / 256, 256>>>((const float4*)Wq, (uint2*)wq_h, (uint2*)wq_l, nw4);
    split_kernel<<<(nw4 + 255) / 256, 256>>>((const float4*)Wo, (uint2*)wo_h, (uint2*)wo_l, nw4);

    const int smem128 = 2 * (2 * 128 + 2 * 128) * STRIDE * 2;  // 81920 B
    const int smem64 = 2 * (2 * 64 + 2 * 128) * STRIDE * 2;    // 61440 B
    cudaFuncSetAttribute(gemm_mma_bf<128>, cudaFuncAttributeMaxDynamicSharedMemorySize, smem128);
    cudaFuncSetAttribute(gemm_mma_bf<64>, cudaFuncAttributeMaxDynamicSharedMemorySize, smem64);

    // fused K + V GEMM (z selects problem)
    GArg gK = {xqk_h, xqk_l, wk_h, wk_l, bk, pk};
    GArg gV = {xv_h, xv_l, wv_h, wv_l, bv, pv};
    gemm_mma_bf<128><<<dim3(D / 128, (n + 127) / 128, 2), 256, smem128>>>(gK, gV, n, D, D, nullptr);

    // Q GEMM (gathered rows)
    GArg gQ = {xqk_h, xqk_l, wq_h, wq_l, bq, pq};
    gemm_mma_bf<64><<<dim3(D / 128, (f + 63) / 64, 1), 256, smem64>>>(gQ, gQ, f, D, D, pidx);

    attn_kernel<<<f, NH * 32>>>(pq, pk, pv, pidx, pnp, prank, pctx, n);
    split_attn_kernel<<<NSPLIT, NH * 32>>>(pq, pk, pv, pelist, pne, pml, pacc, n);
    reduce_attn_kernel<<<dim3(MAXE, NH), DH>>>(pelist, pne, pml, pacc, pctx);

    // split ctx, then O GEMM
    int nf4 = f * D / 4;
    split_kernel<<<(nf4 + 255) / 256, 256>>>((const float4*)pctx, (uint2*)ctx_h, (uint2*)ctx_l, nf4);
    GArg gO = {ctx_h, ctx_l, wo_h, wo_l, bo, (float*)d_out};
    gemm_mma_bf<64><<<dim3(D / 128, (f + 63) / 64, 1), 256, smem64>>>(gO, gO, f, D, D, nullptr);
}

// round 6
// speedup vs baseline: 13.7896x; 1.1257x over previous
#include <cuda_runtime.h>
#include <cuda_bf16.h>
#include <math.h>
#include <stdint.h>

#define D 768
#define NH 12
#define DH 64
#define NMAX 8192
#define MAXE 64
#define NSPLIT 64
#define STRIDE 40  // bf16 elems per smem row (32 + 8 pad)

// fp32 scratch
__device__ float g_k[NMAX * D];
__device__ float g_v[NMAX * D];
__device__ float g_q[NMAX * D];
__device__ float g_ctx[NMAX * D];
__device__ int g_idx[NMAX + 1];
__device__ unsigned char g_npad[NMAX];
__device__ int g_rank[NMAX];
__device__ int g_elist[MAXE];
__device__ int g_ne[1];
__device__ float g_part_ml[MAXE * NH * NSPLIT * 2];
__device__ float g_part_acc[MAXE * NH * NSPLIT * DH];

// bf16 hi/lo pre-split scratch
__device__ __nv_bfloat16 g_xqk_h[NMAX * D], g_xqk_l[NMAX * D];
__device__ __nv_bfloat16 g_xv_h[NMAX * D], g_xv_l[NMAX * D];
__device__ __nv_bfloat16 g_ctx_h[NMAX * D], g_ctx_l[NMAX * D];
__device__ __nv_bfloat16 g_wk_h[D * D], g_wk_l[D * D];
__device__ __nv_bfloat16 g_wv_h[D * D], g_wv_l[D * D];
__device__ __nv_bfloat16 g_wq_h[D * D], g_wq_l[D * D];
__device__ __nv_bfloat16 g_wo_h[D * D], g_wo_l[D * D];

// ---------------------------------------------------------------------------
__device__ __forceinline__ unsigned pack2(__nv_bfloat16 x, __nv_bfloat16 y) {
    __nv_bfloat162 t = __halves2bfloat162(x, y);
    return *reinterpret_cast<unsigned*>(&t);
}

__device__ __forceinline__ void split4(float4 v, uint2& hi, uint2& lo) {
    __nv_bfloat16 h0 = __float2bfloat16_rn(v.x);
    __nv_bfloat16 h1 = __float2bfloat16_rn(v.y);
    __nv_bfloat16 h2 = __float2bfloat16_rn(v.z);
    __nv_bfloat16 h3 = __float2bfloat16_rn(v.w);
    __nv_bfloat16 l0 = __float2bfloat16_rn(v.x - __bfloat162float(h0));
    __nv_bfloat16 l1 = __float2bfloat16_rn(v.y - __bfloat162float(h1));
    __nv_bfloat16 l2 = __float2bfloat16_rn(v.z - __bfloat162float(h2));
    __nv_bfloat16 l3 = __float2bfloat16_rn(v.w - __bfloat162float(h3));
    hi = make_uint2(pack2(h0, h1), pack2(h2, h3));
    lo = make_uint2(pack2(l0, l1), pack2(l2, l3));
}

// single split kernel (fp32 -> bf16 hi/lo)
__global__ void split_kernel(const float4* __restrict__ src, uint2* __restrict__ hi,
                             uint2* __restrict__ lo, int n4) {
    int i = blockIdx.x * blockDim.x + threadIdx.x;
    if (i >= n4) return;
    uint2 h, l;
    split4(src[i], h, l);
    hi[i] = h;
    lo[i] = l;
}

// merged multi-array split (6 jobs, one launch)
struct SplitJobs {
    const float4* src[6];
    uint2* hi[6];
    uint2* lo[6];
    int start[7];  // cumulative float4 offsets
};

__global__ void split_multi_kernel(SplitJobs J) {
    int i = blockIdx.x * blockDim.x + threadIdx.x;
    if (i >= J.start[6]) return;
    int j = 0;
#pragma unroll
    for (int t = 1; t < 6; t++)
        if (i >= J.start[t]) j = t;
    int off = i - J.start[j];
    uint2 h, l;
    split4(J.src[j][off], h, l);
    J.hi[j][off] = h;
    J.lo[j][off] = l;
}

// ---------------------------------------------------------------------------
__global__ void padmask_kernel(const int* __restrict__ ids_raw, int n,
                               const int* __restrict__ padp,
                               unsigned char* __restrict__ npad) {
    int p = blockIdx.x * blockDim.x + threadIdx.x;
    if (p >= n) return;
    int pad = padp[0];
    bool is64 = (n > 1) && (ids_raw[1] == 0);
    long long v = is64 ? ((const long long*)ids_raw)[p] : (long long)ids_raw[p];
    npad[p] = (v != (long long)pad) ? 1 : 0;
}

// ---------------------------------------------------------------------------
__global__ void scan_kernel(const int* __restrict__ qm, int n, int f,
                            int* __restrict__ idxout, int* __restrict__ ne) {
    __shared__ int cnts[256];
    __shared__ int pre[257];
    int t = threadIdx.x;
    int per = (n + 255) / 256;
    int s = t * per;
    int e = s + per; if (e > n) e = n;
    int c = 0;
    for (int p = s; p < e; p++) c += (qm[p] != 0);
    cnts[t] = c;
    __syncthreads();
    if (t == 0) {
        pre[0] = 0;
        for (int i = 0; i < 256; i++) pre[i + 1] = pre[i] + cnts[i];
        ne[0] = 0;
    }
    __syncthreads();
    int rank = pre[t];
    for (int p = s; p < e; p++)
        if (qm[p] != 0) idxout[rank++] = p;
    if (t == 0) idxout[f] = n;
}

// ---------------------------------------------------------------------------
__global__ void flag_empty_kernel(const int* __restrict__ idxarr,
                                  const unsigned char* __restrict__ npad, int f,
                                  int* __restrict__ rank, int* __restrict__ elist,
                                  int* __restrict__ ne) {
    int i = blockIdx.x * blockDim.x + threadIdx.x;
    if (i >= f) return;
    int L = idxarr[i], R = idxarr[i + 1];
    bool any = false;
    for (int p = L; p < R; p++) { if (npad[p]) { any = true; break; } }
    if (any) { rank[i] = -1; return; }
    int r = atomicAdd(ne, 1);
    rank[i] = r;
    if (r < MAXE) elist[r] = i;
}

// ---------------------------------------------------------------------------
// Tensor-core NT GEMM on pre-split bf16 hi/lo operands.
// C[M,N] = A @ B^T + bias, 3-term (AhBh + AhBl + AlBh).
// 8 warps (2m x 4n), mma.m16n8k16, BK=32, BN=128, BM templated.
// 3-stage cp.async ring, ldmatrix fragment loads, one sync per iter.
// blockIdx.z selects problem (up to 3 fused).
// ---------------------------------------------------------------------------
struct GArg {
    const __nv_bfloat16 *Ah, *Al, *Bh, *Bl;
    const float* bias;
    float* C;
    int M;
    const int* rowmap;
};

__device__ __forceinline__ void mma_bf16(float* d, const unsigned* a, const unsigned* b) {
    asm volatile(
        "mma.sync.aligned.m16n8k16.row.col.f32.bf16.bf16.f32 "
        "{%0,%1,%2,%3}, {%4,%5,%6,%7}, {%8,%9}, {%0,%1,%2,%3};\n"
        : "+f"(d[0]), "+f"(d[1]), "+f"(d[2]), "+f"(d[3])
        : "r"(a[0]), "r"(a[1]), "r"(a[2]), "r"(a[3]), "r"(b[0]), "r"(b[1]));
}

__device__ __forceinline__ void ldmx4(unsigned* r, unsigned saddr) {
    asm volatile(
        "ldmatrix.sync.aligned.m8n8.x4.shared.b16 {%0,%1,%2,%3}, [%4];\n"
        : "=r"(r[0]), "=r"(r[1]), "=r"(r[2]), "=r"(r[3]) : "r"(saddr));
}

__device__ __forceinline__ void cp_async16(__nv_bfloat16* dst, const __nv_bfloat16* src) {
    unsigned s = (unsigned)__cvta_generic_to_shared(dst);
    asm volatile("cp.async.cg.shared.global [%0], [%1], 16;\n" :: "r"(s), "l"(src));
}

template <int BM>
__global__ __launch_bounds__(256)
void gemm_mma_bf(GArg g0, GArg g1, GArg g2, int N, int K) {
    const int WM = BM / 2;
    const int MT = WM / 16;
    const int ASZ = BM * STRIDE;       // elems
    const int BSZ = 128 * STRIDE;      // elems
    const int STG = 2 * ASZ + 2 * BSZ; // elems per stage
    extern __shared__ __nv_bfloat16 smraw[];

    GArg G = (blockIdx.z == 0) ? g0 : ((blockIdx.z == 1) ? g1 : g2);
    int M = G.M;
    int m0 = blockIdx.y * BM;
    if (m0 >= M) return;
    int n0 = blockIdx.x * 128;

    int tid = threadIdx.x;
    int warp = tid >> 5;
    int lane = tid & 31;
    int g = lane >> 2;
    int tig = lane & 3;
    int wm = warp >> 2;
    int wn = warp & 3;

    const int* rowmap = G.rowmap;

    float acc[MT][4][4];
#pragma unroll
    for (int i = 0; i < MT; i++)
#pragma unroll
        for (int j = 0; j < 4; j++)
#pragma unroll
            for (int r = 0; r < 4; r++) acc[i][j][r] = 0.f;

    // ---- stage loader: BK=32 bf16 per row = 4 x 16B chunks
    auto load_stage = [&](int st, int k0) {
        __nv_bfloat16* base = smraw + st * STG;
#pragma unroll
        for (int c = tid; c < BM * 4; c += 256) {
            int r = c >> 2, ch = c & 3;
            int gr = m0 + r;
            if (gr >= M) gr = M - 1;  // clamp: junk rows discarded at epilogue
            int ar = rowmap ? rowmap[gr] : gr;
            size_t go = (size_t)ar * K + k0 + ch * 8;
            int dst = r * STRIDE + ch * 8;
            cp_async16(base + dst, G.Ah + go);
            cp_async16(base + ASZ + dst, G.Al + go);
        }
#pragma unroll
        for (int c = tid; c < 128 * 4; c += 256) {
            int r = c >> 2, ch = c & 3;
            size_t go = (size_t)(n0 + r) * K + k0 + ch * 8;
            int dst = r * STRIDE + ch * 8;
            cp_async16(base + 2 * ASZ + dst, G.Bh + go);
            cp_async16(base + 2 * ASZ + BSZ + dst, G.Bl + go);
        }
        asm volatile("cp.async.commit_group;\n");
    };

    // ldmatrix per-lane offsets (element units)
    unsigned smem_u32 = (unsigned)__cvta_generic_to_shared(smraw);
    int frow = lane & 15;
    int fcolA = (lane & 16) ? 8 : 0;
    unsigned aOff = ((unsigned)((wm * WM + frow) * STRIDE + fcolA)) * 2;
    int bn = wn * 32 + ((lane & 16) ? 8 : 0) + (lane & 7);
    unsigned bColSel = (lane & 8) ? 8 : 0;
    unsigned bOff = ((unsigned)(bn * STRIDE) + bColSel) * 2;

    int nk = K / 32;
    load_stage(0, 0);
    load_stage(1, 32);

    for (int i = 0; i < nk; i++) {
        if (i + 2 < nk) {
            asm volatile("cp.async.wait_group 1;\n");
        } else {
            asm volatile("cp.async.wait_group 0;\n");
        }
        __syncthreads();

        unsigned bufb = smem_u32 + (unsigned)((i % 3) * STG) * 2;
        unsigned aBaseH = bufb + aOff;
        unsigned aBaseL = aBaseH + (unsigned)ASZ * 2;
        unsigned bBaseH = bufb + (unsigned)(2 * ASZ) * 2 + bOff;
        unsigned bBaseL = bBaseH + (unsigned)BSZ * 2;

#pragma unroll
        for (int ks = 0; ks < 2; ks++) {
            unsigned koff = ks * 32;  // 16 elems * 2B
            unsigned bh[8], bl[8];
            ldmx4(&bh[0], bBaseH + koff);                       // nt0, nt1
            ldmx4(&bh[4], bBaseH + 16 * STRIDE * 2 + koff);     // nt2, nt3
            ldmx4(&bl[0], bBaseL + koff);
            ldmx4(&bl[4], bBaseL + 16 * STRIDE * 2 + koff);
#pragma unroll
            for (int mt = 0; mt < MT; mt++) {
                unsigned ah[4], al[4];
                unsigned moff = (unsigned)(mt * 16 * STRIDE) * 2 + koff;
                ldmx4(ah, aBaseH + moff);
                ldmx4(al, aBaseL + moff);
#pragma unroll
                for (int nt = 0; nt < 4; nt++) mma_bf16(acc[mt][nt], ah, &bh[nt * 2]);
#pragma unroll
                for (int nt = 0; nt < 4; nt++) mma_bf16(acc[mt][nt], ah, &bl[nt * 2]);
#pragma unroll
                for (int nt = 0; nt < 4; nt++) mma_bf16(acc[mt][nt], al, &bh[nt * 2]);
            }
        }

        if (i + 2 < nk) load_stage((i + 2) % 3, (i + 2) * 32);
        // next iteration's top sync protects the ring buffer
    }

    // ---- epilogue
#pragma unroll
    for (int mt = 0; mt < MT; mt++) {
#pragma unroll
        for (int nt = 0; nt < 4; nt++) {
            int row = m0 + wm * WM + mt * 16 + g;
            int col = n0 + wn * 32 + nt * 8 + 2 * tig;
            float b0 = G.bias[col], b1 = G.bias[col + 1];
            if (row < M) {
                float2 o = make_float2(acc[mt][nt][0] + b0, acc[mt][nt][1] + b1);
                *(float2*)(G.C + (size_t)row * N + col) = o;
            }
            if (row + 8 < M) {
                float2 o = make_float2(acc[mt][nt][2] + b0, acc[mt][nt][3] + b1);
                *(float2*)(G.C + (size_t)(row + 8) * N + col) = o;
            }
        }
    }
}

// ---------------------------------------------------------------------------
// normal attention: one block per feature, one warp per head.
// Scores cached in smem so K is read once (segments <= 32 keys).
// ---------------------------------------------------------------------------
__global__ __launch_bounds__(NH * 32)
void attn_kernel(const float* __restrict__ q, const float* __restrict__ k,
                 const float* __restrict__ v, const int* __restrict__ idxarr,
                 const unsigned char* __restrict__ npad,
                 const int* __restrict__ rankarr,
                 float* __restrict__ ctx, int n) {
    int i = blockIdx.x;
    int rk = rankarr[i];
    if (rk >= 0 && rk < MAXE) return;  // split path
    int h = threadIdx.x / 32;
    int lane = threadIdx.x % 32;

    __shared__ float qsh[NH][DH];
    __shared__ float ssh[NH][32];
    const float* qb = q + (size_t)i * D + h * DH;
    qsh[h][lane] = qb[lane];
    qsh[h][lane + 32] = qb[lane + 32];
    __syncwarp();

    int left = idxarr[i];
    int right = idxarr[i + 1];
    int seglen = right - left;
    float q0 = qsh[h][lane];
    float q1 = qsh[h][lane + 32];
    const float scale = 0.125f;

    float m = -1e30f;
    int cnt = 0;
    bool cache = (seglen <= 32);
    for (int p = left; p < right; p++) {
        if (!npad[p]) continue;
        const float* kb = k + (size_t)p * D + h * DH;
        float part = q0 * kb[lane] + q1 * kb[lane + 32];
#pragma unroll
        for (int o = 16; o > 0; o >>= 1) part += __shfl_xor_sync(0xffffffffu, part, o);
        float s = part * scale;
        if (cache && lane == 0) ssh[h][cnt] = s;
        cnt++;
        if (s > m) m = s;
    }
    __syncwarp();

    if (cnt > 0) {
        float l = 0.f, a0 = 0.f, a1 = 0.f;
        int c = 0;
        for (int p = left; p < right; p++) {
            if (!npad[p]) continue;
            float s;
            if (cache) {
                s = ssh[h][c++];
            } else {
                const float* kb = k + (size_t)p * D + h * DH;
                float part = q0 * kb[lane] + q1 * kb[lane + 32];
#pragma unroll
                for (int o = 16; o > 0; o >>= 1) part += __shfl_xor_sync(0xffffffffu, part, o);
                s = part * scale;
            }
            float e = expf(s - m);
            const float* vb = v + (size_t)p * D + h * DH;
            l += e;
            a0 += e * vb[lane];
            a1 += e * vb[lane + 32];
        }
        ctx[(size_t)i * D + h * DH + lane] = a0 / l;
        ctx[(size_t)i * D + h * DH + lane + 32] = a1 / l;
    } else {
        // overflow fallback (rank >= MAXE): full softmax over all n keys
        float m_i = -1e30f, l_i = 0.f;
        float acc[DH];
#pragma unroll
        for (int d = 0; d < DH; d++) acc[d] = 0.f;
        for (int p = lane; p < n; p += 32) {
            const float* kb = k + (size_t)p * D + h * DH;
            float s = 0.f;
#pragma unroll
            for (int d = 0; d < DH; d++) s += qsh[h][d] * kb[d];
            s *= scale;
            if (s > m_i) {
                float c = expf(m_i - s);
                l_i *= c;
#pragma unroll
                for (int d = 0; d < DH; d++) acc[d] *= c;
                m_i = s;
            }
            float e = expf(s - m_i);
            const float* vb = v + (size_t)p * D + h * DH;
            l_i += e;
#pragma unroll
            for (int d = 0; d < DH; d++) acc[d] += e * vb[d];
        }
        float M_ = m_i;
#pragma unroll
        for (int o = 16; o > 0; o >>= 1) M_ = fmaxf(M_, __shfl_xor_sync(0xffffffffu, M_, o));
        float c = expf(m_i - M_);
        float lt = l_i * c;
#pragma unroll
        for (int o = 16; o > 0; o >>= 1) lt += __shfl_xor_sync(0xffffffffu, lt, o);
#pragma unroll
        for (int d = 0; d < DH; d++) {
            float vs = acc[d] * c;
#pragma unroll
            for (int o = 16; o > 0; o >>= 1) vs += __shfl_xor_sync(0xffffffffu, vs, o);
            if (lane == 0) ctx[(size_t)i * D + h * DH + d] = vs / lt;
        }
    }
}

// ---------------------------------------------------------------------------
// split-K flash decode for fully-masked features
// ---------------------------------------------------------------------------
__global__ __launch_bounds__(NH * 32)
void split_attn_kernel(const float* __restrict__ q, const float* __restrict__ k,
                       const float* __restrict__ v, const int* __restrict__ elist,
                       const int* __restrict__ nep,
                       float* __restrict__ part_ml, float* __restrict__ part_acc,
                       int n) {
    int split = blockIdx.x;
    int h = threadIdx.x / 32;
    int lane = threadIdx.x % 32;
    int ne = nep[0];
    if (ne > MAXE) ne = MAXE;
    if (ne == 0) return;
    int chunk = (n + NSPLIT - 1) / NSPLIT;
    int ks = split * chunk;
    int ke = ks + chunk; if (ke > n) ke = n;
    const float scale = 0.125f;

    for (int e0 = 0; e0 < ne; e0 += 8) {
        int gs = ne - e0; if (gs > 8) gs = 8;
        float q0[8], q1[8], m_[8], l_[8], a0[8], a1[8];
#pragma unroll
        for (int j = 0; j < 8; j++) {
            if (j < gs) {
                int ft = elist[e0 + j];
                q0[j] = q[(size_t)ft * D + h * DH + lane];
                q1[j] = q[(size_t)ft * D + h * DH + lane + 32];
            } else { q0[j] = 0.f; q1[j] = 0.f; }
            m_[j] = -1e30f; l_[j] = 0.f; a0[j] = 0.f; a1[j] = 0.f;
        }
        for (int p = ks; p < ke; p++) {
            const float* kb = k + (size_t)p * D + h * DH;
            const float* vb = v + (size_t)p * D + h * DH;
            float k0 = kb[lane], k1 = kb[lane + 32];
            float v0 = vb[lane], v1 = vb[lane + 32];
            float s[8];
#pragma unroll
            for (int j = 0; j < 8; j++) s[j] = q0[j] * k0 + q1[j] * k1;
#pragma unroll
            for (int o = 16; o > 0; o >>= 1)
#pragma unroll
                for (int j = 0; j < 8; j++) s[j] += __shfl_xor_sync(0xffffffffu, s[j], o);
#pragma unroll
            for (int j = 0; j < 8; j++) {
                float sc = s[j] * scale;
                float mn = fmaxf(m_[j], sc);
                float corr = expf(m_[j] - mn);
                float e = expf(sc - mn);
                l_[j] = l_[j] * corr + e;
                a0[j] = a0[j] * corr + e * v0;
                a1[j] = a1[j] * corr + e * v1;
                m_[j] = mn;
            }
        }
#pragma unroll
        for (int j = 0; j < 8; j++) {
            if (j >= gs) continue;
            size_t base = ((size_t)(e0 + j) * NH + h) * NSPLIT + split;
            if (lane == 0) { part_ml[base * 2] = m_[j]; part_ml[base * 2 + 1] = l_[j]; }
            part_acc[base * DH + lane] = a0[j];
            part_acc[base * DH + lane + 32] = a1[j];
        }
    }
}

__global__ __launch_bounds__(DH)
void reduce_attn_kernel(const int* __restrict__ elist, const int* __restrict__ nep,
                        const float* __restrict__ part_ml,
                        const float* __restrict__ part_acc,
                        float* __restrict__ ctx) {
    int e = blockIdx.x, h = blockIdx.y;
    int ne = nep[0]; if (ne > MAXE) ne = MAXE;
    if (e >= ne) return;
    int d = threadIdx.x;
    __shared__ float wsh[NSPLIT];
    __shared__ float Lsh;
    if (d == 0) {
        float M = -1e30f;
        size_t mb = ((size_t)e * NH + h) * NSPLIT;
        for (int s = 0; s < NSPLIT; s++) {
            float m = part_ml[(mb + s) * 2];
            if (m > M) M = m;
        }
        float L = 0.f;
        for (int s = 0; s < NSPLIT; s++) {
            float m = part_ml[(mb + s) * 2];
            float l = part_ml[(mb + s) * 2 + 1];
            float w = expf(m - M);
            wsh[s] = w;
            L += w * l;
        }
        Lsh = L;
    }
    __syncthreads();
    float acc = 0.f;
    size_t ab = ((size_t)e * NH + h) * NSPLIT;
    for (int s = 0; s < NSPLIT; s++) acc += wsh[s] * part_acc[(ab + s) * DH + d];
    int ft = elist[e];
    ctx[(size_t)ft * D + h * DH + d] = acc / Lsh;
}

// ---------------------------------------------------------------------------
extern "C" void kernel_launch(void* const* d_in, const int* in_sizes, int n_in,
                              void* d_out, int out_size) {
    const float* x_qk = (const float*)d_in[0];
    const float* x_v = (const float*)d_in[1];
    const int* qm = (const int*)d_in[2];
    const int* ids = (const int*)d_in[3];
    const int* padp = (const int*)d_in[4];
    const float* Wq = (const float*)d_in[5];
    const float* bq = (const float*)d_in[6];
    const float* Wk = (const float*)d_in[7];
    const float* bk = (const float*)d_in[8];
    const float* Wv = (const float*)d_in[9];
    const float* bv = (const float*)d_in[10];
    const float* Wo = (const float*)d_in[11];
    const float* bo = (const float*)d_in[12];

    int n = in_sizes[0] / D;
    int f = out_size / D;

    float *pk, *pv, *pq, *pctx, *pml, *pacc;
    int *pidx, *prank, *pelist, *pne;
    unsigned char* pnp;
    cudaGetSymbolAddress((void**)&pk, g_k);
    cudaGetSymbolAddress((void**)&pv, g_v);
    cudaGetSymbolAddress((void**)&pq, g_q);
    cudaGetSymbolAddress((void**)&pctx, g_ctx);
    cudaGetSymbolAddress((void**)&pidx, g_idx);
    cudaGetSymbolAddress((void**)&pnp, g_npad);
    cudaGetSymbolAddress((void**)&prank, g_rank);
    cudaGetSymbolAddress((void**)&pelist, g_elist);
    cudaGetSymbolAddress((void**)&pne, g_ne);
    cudaGetSymbolAddress((void**)&pml, g_part_ml);
    cudaGetSymbolAddress((void**)&pacc, g_part_acc);

    __nv_bfloat16 *xqk_h, *xqk_l, *xv_h, *xv_l, *ctx_h, *ctx_l;
    __nv_bfloat16 *wk_h, *wk_l, *wv_h, *wv_l, *wq_h, *wq_l, *wo_h, *wo_l;
    cudaGetSymbolAddress((void**)&xqk_h, g_xqk_h);
    cudaGetSymbolAddress((void**)&xqk_l, g_xqk_l);
    cudaGetSymbolAddress((void**)&xv_h, g_xv_h);
    cudaGetSymbolAddress((void**)&xv_l, g_xv_l);
    cudaGetSymbolAddress((void**)&ctx_h, g_ctx_h);
    cudaGetSymbolAddress((void**)&ctx_l, g_ctx_l);
    cudaGetSymbolAddress((void**)&wk_h, g_wk_h);
    cudaGetSymbolAddress((void**)&wk_l, g_wk_l);
    cudaGetSymbolAddress((void**)&wv_h, g_wv_h);
    cudaGetSymbolAddress((void**)&wv_l, g_wv_l);
    cudaGetSymbolAddress((void**)&wq_h, g_wq_h);
    cudaGetSymbolAddress((void**)&wq_l, g_wq_l);
    cudaGetSymbolAddress((void**)&wo_h, g_wo_h);
    cudaGetSymbolAddress((void**)&wo_l, g_wo_l);

    padmask_kernel<<<(n + 255) / 256, 256>>>(ids, n, padp, pnp);
    scan_kernel<<<1, 256>>>(qm, n, f, pidx, pne);
    flag_empty_kernel<<<(f + 255) / 256, 256>>>(pidx, pnp, f, prank, pelist, pne);

    // merged pre-split of inputs + weights
    int nx4 = n * D / 4;
    int nw4 = D * D / 4;
    SplitJobs J;
    J.src[0] = (const float4*)x_qk; J.hi[0] = (uint2*)xqk_h; J.lo[0] = (uint2*)xqk_l;
    J.src[1] = (const float4*)x_v;  J.hi[1] = (uint2*)xv_h;  J.lo[1] = (uint2*)xv_l;
    J.src[2] = (const float4*)Wk;   J.hi[2] = (uint2*)wk_h;  J.lo[2] = (uint2*)wk_l;
    J.src[3] = (const float4*)Wv;   J.hi[3] = (uint2*)wv_h;  J.lo[3] = (uint2*)wv_l;
    J.src[4] = (const float4*)Wq;   J.hi[4] = (uint2*)wq_h;  J.lo[4] = (uint2*)wq_l;
    J.src[5] = (const float4*)Wo;   J.hi[5] = (uint2*)wo_h;  J.lo[5] = (uint2*)wo_l;
    J.start[0] = 0;
    J.start[1] = nx4;
    J.start[2] = 2 * nx4;
    J.start[3] = 2 * nx4 + nw4;
    J.start[4] = 2 * nx4 + 2 * nw4;
    J.start[5] = 2 * nx4 + 3 * nw4;
    J.start[6] = 2 * nx4 + 4 * nw4;
    split_multi_kernel<<<(J.start[6] + 255) / 256, 256>>>(J);

    // smem: 3 stages
    const int smem128 = 3 * (2 * 128 + 2 * 128) * STRIDE * 2;  // 122880 B
    const int smem64 = 3 * (2 * 64 + 2 * 128) * STRIDE * 2;    // 92160 B
    cudaFuncSetAttribute(gemm_mma_bf<128>, cudaFuncAttributeMaxDynamicSharedMemorySize, smem128);
    cudaFuncSetAttribute(gemm_mma_bf<64>, cudaFuncAttributeMaxDynamicSharedMemorySize, smem64);

    // fused K + V + Q GEMM (z selects problem; per-z M/rowmap)
    GArg gK = {xqk_h, xqk_l, wk_h, wk_l, bk, pk, n, nullptr};
    GArg gV = {xv_h, xv_l, wv_h, wv_l, bv, pv, n, nullptr};
    GArg gQ = {xqk_h, xqk_l, wq_h, wq_l, bq, pq, f, pidx};
    gemm_mma_bf<128><<<dim3(D / 128, (n + 127) / 128, 3), 256, smem128>>>(gK, gV, gQ, D, D);

    attn_kernel<<<f, NH * 32>>>(pq, pk, pv, pidx, pnp, prank, pctx, n);
    split_attn_kernel<<<NSPLIT, NH * 32>>>(pq, pk, pv, pelist, pne, pml, pacc, n);
    reduce_attn_kernel<<<dim3(MAXE, NH), DH>>>(pelist, pne, pml, pacc, pctx);

    // split ctx, then O GEMM
    int nf4 = f * D / 4;
    split_kernel<<<(nf4 + 255) / 256, 256>>>((const float4*)pctx, (uint2*)ctx_h, (uint2*)ctx_l, nf4);
    GArg gO = {ctx_h, ctx_l, wo_h, wo_l, bo, (float*)d_out, f, nullptr};
    gemm_mma_bf<64><<<dim3(D / 128, (f + 63) / 64, 1), 256, smem64>>>(gO, gO, gO, D, D);
}